// round 1
// baseline (speedup 1.0000x reference)
#include <cuda_runtime.h>
#include <cuda_bf16.h>
#include <math.h>

// ---------------- problem constants ----------------
#define BB 4
#define SS 512
#define DD 768
#define HH 12
#define LL 12
#define FF 3072
#define DH 64
#define PP 512        // rel-embedding rows (2*BUCKETS)
#define BH (BB*HH)    // 48
#define MM (BB*SS)    // 2048 tokens

// ---------------- device scratch (allocation-free rule: __device__ globals) ----------------
__device__ float g_h   [MM*DD];
__device__ float g_q   [MM*DD];
__device__ float g_k   [MM*DD];
__device__ float g_v   [MM*DD];
__device__ float g_ctx [MM*DD];
__device__ float g_tmp [MM*FF];
__device__ float g_posk[PP*DD];
__device__ float g_posq[PP*DD];
__device__ float g_scores[(size_t)BH*SS*SS];
__device__ float g_c2p   [(size_t)BH*SS*SS];
__device__ float g_p2c   [(size_t)BH*SS*SS];
__device__ int   g_c2pi[SS*SS];
__device__ int   g_p2ci[SS*SS];

// ---------------- embeddings + LayerNorm + mask ----------------
__global__ void __launch_bounds__(256) embed_ln_kernel(
    const int* __restrict__ ids, const int* __restrict__ segs, const int* __restrict__ pins,
    const float* __restrict__ mask,
    const float* __restrict__ tok, const float* __restrict__ pin, const float* __restrict__ seg,
    const float* __restrict__ w, const float* __restrict__ b, float* __restrict__ out)
{
    int t = blockIdx.x;                 // token index 0..MM-1
    int tid = threadIdx.x;
    __shared__ float xs[DD];
    __shared__ float red[256];

    size_t io = (size_t)ids[t]  * DD;
    size_t po = (size_t)pins[t] * DD;
    size_t so = (size_t)segs[t] * DD;

    float s = 0.f;
    for (int d = tid; d < DD; d += 256) {
        float x = tok[io + d] + pin[po + d] + seg[so + d];
        xs[d] = x; s += x;
    }
    red[tid] = s; __syncthreads();
    for (int st = 128; st > 0; st >>= 1) { if (tid < st) red[tid] += red[tid + st]; __syncthreads(); }
    float mu = red[0] * (1.0f / DD); __syncthreads();

    float s2 = 0.f;
    for (int d = tid; d < DD; d += 256) { float dv = xs[d] - mu; s2 += dv * dv; }
    red[tid] = s2; __syncthreads();
    for (int st = 128; st > 0; st >>= 1) { if (tid < st) red[tid] += red[tid + st]; __syncthreads(); }
    float inv = rsqrtf(red[0] * (1.0f / DD) + 1e-12f);

    float m = mask[t];
    for (int d = tid; d < DD; d += 256)
        out[(size_t)t * DD + d] = ((xs[d] - mu) * inv * w[d] + b[d]) * m;
}

// ---------------- relative-position bucketing (DeBERTa-v2 log buckets) ----------------
__global__ void relpos_kernel(int* __restrict__ c2pi, int* __restrict__ p2ci)
{
    int j = blockIdx.x * blockDim.x + threadIdx.x;  // key index
    int i = blockIdx.y;                             // query index
    if (j >= SS) return;
    int rel = i - j;
    const int mid = 128;                            // BUCKETS/2
    int ap = (rel < mid && rel > -mid) ? (mid - 1) : (rel < 0 ? -rel : rel);
    int bucket;
    if (ap <= mid) {
        bucket = rel;
    } else {
        double lp = ceil(log((double)ap / (double)mid) / log(511.0 / 128.0) * (mid - 1)) + mid;
        int sgn = (rel > 0) - (rel < 0);
        bucket = (int)lp * sgn;
    }
    int c = bucket + 256;  c = c < 0 ? 0 : (c > 511 ? 511 : c);
    int p = -bucket + 256; p = p < 0 ? 0 : (p > 511 ? 511 : p);
    c2pi[i * SS + j] = c;
    p2ci[i * SS + j] = p;
}

// ---------------- generic dense GEMM: C[M,N] = A[M,K] * B[K,N] + bias, opt exact GELU ----------------
// 128x128 block tile, 8-deep K slices, 8x8 per-thread microtile. M,N,K all multiples of 128/8 here.
__global__ void __launch_bounds__(256) gemm_nn(
    const float* __restrict__ A, const float* __restrict__ Bm,
    const float* __restrict__ bias, float* __restrict__ C,
    int M, int N, int K, int act)
{
    __shared__ float As[8][128];
    __shared__ float Bs[8][128];
    int tid = threadIdx.x;
    int m0 = blockIdx.y * 128, n0 = blockIdx.x * 128;

    int arow = tid >> 1;            // 0..127
    int acol = (tid & 1) * 4;       // 0 / 4
    int brow = tid >> 5;            // 0..7
    int bcol = (tid & 31) * 4;      // 0..124
    int ty = tid >> 4, tx = tid & 15;

    float acc[8][8];
    #pragma unroll
    for (int i = 0; i < 8; i++)
        #pragma unroll
        for (int j = 0; j < 8; j++) acc[i][j] = 0.f;

    for (int kt = 0; kt < K; kt += 8) {
        float4 av = *reinterpret_cast<const float4*>(A + (size_t)(m0 + arow) * K + kt + acol);
        As[acol + 0][arow] = av.x; As[acol + 1][arow] = av.y;
        As[acol + 2][arow] = av.z; As[acol + 3][arow] = av.w;
        float4 bv = *reinterpret_cast<const float4*>(Bm + (size_t)(kt + brow) * N + n0 + bcol);
        *reinterpret_cast<float4*>(&Bs[brow][bcol]) = bv;
        __syncthreads();
        #pragma unroll
        for (int kk = 0; kk < 8; kk++) {
            float a[8], bb[8];
            #pragma unroll
            for (int i = 0; i < 8; i++) a[i] = As[kk][ty * 8 + i];
            #pragma unroll
            for (int j = 0; j < 8; j++) bb[j] = Bs[kk][tx * 8 + j];
            #pragma unroll
            for (int i = 0; i < 8; i++)
                #pragma unroll
                for (int j = 0; j < 8; j++) acc[i][j] = fmaf(a[i], bb[j], acc[i][j]);
        }
        __syncthreads();
    }

    #pragma unroll
    for (int i = 0; i < 8; i++) {
        int m = m0 + ty * 8 + i;
        #pragma unroll
        for (int j = 0; j < 8; j++) {
            int n = n0 + tx * 8 + j;
            float v = acc[i][j] + (bias ? bias[n] : 0.f);
            if (act == 1) v = 0.5f * v * (1.0f + erff(v * 0.70710678118654752f));
            C[(size_t)m * N + n] = v;
        }
    }
}

// ---------------- batched score GEMM: C[z, m, n] = scale * sum_d A[b,m,h,d] * B[(b?),n,h,d] ----------------
// A: [B,S,H,DH] flattened via stride DD. B either batched like A (bBatch=1: keys) or shared [P,H,DH] (bBatch=0).
__global__ void __launch_bounds__(256) score_gemm(
    const float* __restrict__ Ab, const float* __restrict__ Bb,
    float* __restrict__ Cb, int bBatch, float scale)
{
    int z = blockIdx.z; int b = z / HH, hh = z % HH;
    const float* A  = Ab + (size_t)b * SS * DD + hh * DH;
    const float* Bm = Bb + (bBatch ? (size_t)b * SS * DD : 0) + hh * DH;
    float* C = Cb + (size_t)z * SS * SS;
    int m0 = blockIdx.y * 64, n0 = blockIdx.x * 64;

    __shared__ float As[16][64];
    __shared__ float Bs[16][64];
    int tid = threadIdx.x;
    int row = tid >> 2;             // 0..63
    int kc  = (tid & 3) * 4;        // 0..12
    int ty = tid >> 4, tx = tid & 15;

    float acc[4][4];
    #pragma unroll
    for (int i = 0; i < 4; i++)
        #pragma unroll
        for (int j = 0; j < 4; j++) acc[i][j] = 0.f;

    for (int kt = 0; kt < DH; kt += 16) {
        float4 av = *reinterpret_cast<const float4*>(A + (size_t)(m0 + row) * DD + kt + kc);
        As[kc + 0][row] = av.x; As[kc + 1][row] = av.y; As[kc + 2][row] = av.z; As[kc + 3][row] = av.w;
        float4 bv = *reinterpret_cast<const float4*>(Bm + (size_t)(n0 + row) * DD + kt + kc);
        Bs[kc + 0][row] = bv.x; Bs[kc + 1][row] = bv.y; Bs[kc + 2][row] = bv.z; Bs[kc + 3][row] = bv.w;
        __syncthreads();
        #pragma unroll
        for (int kk = 0; kk < 16; kk++) {
            float a[4], bb[4];
            #pragma unroll
            for (int i = 0; i < 4; i++) a[i] = As[kk][ty * 4 + i];
            #pragma unroll
            for (int j = 0; j < 4; j++) bb[j] = Bs[kk][tx * 4 + j];
            #pragma unroll
            for (int i = 0; i < 4; i++)
                #pragma unroll
                for (int j = 0; j < 4; j++) acc[i][j] = fmaf(a[i], bb[j], acc[i][j]);
        }
        __syncthreads();
    }
    #pragma unroll
    for (int i = 0; i < 4; i++)
        #pragma unroll
        for (int j = 0; j < 4; j++)
            C[(size_t)(m0 + ty * 4 + i) * SS + n0 + tx * 4 + j] = acc[i][j] * scale;
}

// ---------------- fused c2p/p2c gather + mask + softmax (in-place on scores) ----------------
__global__ void __launch_bounds__(256) softmax_gather(
    float* __restrict__ scores, const float* __restrict__ c2p, const float* __restrict__ p2c,
    const int* __restrict__ c2pi, const int* __restrict__ p2ci, const float* __restrict__ mask)
{
    int q = blockIdx.x, z = blockIdx.y;
    int b = z / HH;
    int t = threadIdx.x;
    float* srow = scores + ((size_t)z * SS + q) * SS;
    const float* crow = c2p + ((size_t)z * SS + q) * SS;

    float v[2];
    #pragma unroll
    for (int e = 0; e < 2; e++) {
        int k = t + e * 256;
        float s = srow[k]
                + crow[c2pi[q * SS + k]]
                + p2c[((size_t)z * SS + k) * SS + p2ci[k * SS + q]]
                + (1.0f - mask[b * SS + k]) * (-1e9f);
        v[e] = s;
    }
    __shared__ float red[256];
    red[t] = fmaxf(v[0], v[1]); __syncthreads();
    for (int st = 128; st > 0; st >>= 1) { if (t < st) red[t] = fmaxf(red[t], red[t + st]); __syncthreads(); }
    float mx = red[0]; __syncthreads();
    float e0 = expf(v[0] - mx), e1 = expf(v[1] - mx);
    red[t] = e0 + e1; __syncthreads();
    for (int st = 128; st > 0; st >>= 1) { if (t < st) red[t] += red[t + st]; __syncthreads(); }
    float inv = 1.0f / red[0];
    srow[t]       = e0 * inv;
    srow[t + 256] = e1 * inv;
}

// ---------------- batched ctx GEMM: O[b,m,h,:] = sum_k P[z,m,k] * V[b,k,h,:] ----------------
__global__ void __launch_bounds__(256) ctx_gemm(
    const float* __restrict__ Pm, const float* __restrict__ V, float* __restrict__ O)
{
    int z = blockIdx.y; int b = z / HH, hh = z % HH;
    int m0 = blockIdx.x * 64;
    const float* A = Pm + (size_t)z * SS * SS;

    __shared__ float As[16][64];
    __shared__ float Bs[16][64];
    int tid = threadIdx.x;
    int arow = tid >> 2, akc = (tid & 3) * 4;
    int bk = tid >> 4, bn = (tid & 15) * 4;
    int ty = tid >> 4, tx = tid & 15;

    float acc[4][4];
    #pragma unroll
    for (int i = 0; i < 4; i++)
        #pragma unroll
        for (int j = 0; j < 4; j++) acc[i][j] = 0.f;

    for (int kt = 0; kt < SS; kt += 16) {
        float4 av = *reinterpret_cast<const float4*>(A + (size_t)(m0 + arow) * SS + kt + akc);
        As[akc + 0][arow] = av.x; As[akc + 1][arow] = av.y; As[akc + 2][arow] = av.z; As[akc + 3][arow] = av.w;
        float4 bv = *reinterpret_cast<const float4*>(V + ((size_t)b * SS + kt + bk) * DD + hh * DH + bn);
        *reinterpret_cast<float4*>(&Bs[bk][bn]) = bv;
        __syncthreads();
        #pragma unroll
        for (int kk = 0; kk < 16; kk++) {
            float a[4], bb[4];
            #pragma unroll
            for (int i = 0; i < 4; i++) a[i] = As[kk][ty * 4 + i];
            #pragma unroll
            for (int j = 0; j < 4; j++) bb[j] = Bs[kk][tx * 4 + j];
            #pragma unroll
            for (int i = 0; i < 4; i++)
                #pragma unroll
                for (int j = 0; j < 4; j++) acc[i][j] = fmaf(a[i], bb[j], acc[i][j]);
        }
        __syncthreads();
    }
    #pragma unroll
    for (int i = 0; i < 4; i++)
        #pragma unroll
        for (int j = 0; j < 4; j++)
            O[((size_t)b * SS + m0 + ty * 4 + i) * DD + hh * DH + tx * 4 + j] = acc[i][j];
}

// ---------------- residual add + LayerNorm (in-place on h) ----------------
__global__ void __launch_bounds__(256) add_ln_kernel(
    float* __restrict__ h, const float* __restrict__ delta,
    const float* __restrict__ w, const float* __restrict__ b)
{
    int t = blockIdx.x;
    int tid = threadIdx.x;
    __shared__ float xs[DD];
    __shared__ float red[256];
    float* hr = h + (size_t)t * DD;
    const float* dr = delta + (size_t)t * DD;

    float s = 0.f;
    for (int d = tid; d < DD; d += 256) { float x = hr[d] + dr[d]; xs[d] = x; s += x; }
    red[tid] = s; __syncthreads();
    for (int st = 128; st > 0; st >>= 1) { if (tid < st) red[tid] += red[tid + st]; __syncthreads(); }
    float mu = red[0] * (1.0f / DD); __syncthreads();

    float s2 = 0.f;
    for (int d = tid; d < DD; d += 256) { float dv = xs[d] - mu; s2 += dv * dv; }
    red[tid] = s2; __syncthreads();
    for (int st = 128; st > 0; st >>= 1) { if (tid < st) red[tid] += red[tid + st]; __syncthreads(); }
    float inv = rsqrtf(red[0] * (1.0f / DD) + 1e-12f);

    for (int d = tid; d < DD; d += 256) hr[d] = (xs[d] - mu) * inv * w[d] + b[d];
}

// ---------------- host orchestration ----------------
extern "C" void kernel_launch(void* const* d_in, const int* in_sizes, int n_in,
                              void* d_out, int out_size)
{
    const int*   input_ids   = (const int*)  d_in[0];
    const int*   segment_ids = (const int*)  d_in[1];
    const int*   pinyin_ids  = (const int*)  d_in[2];
    const float* attn_mask   = (const float*)d_in[3];
    const float* tok_emb     = (const float*)d_in[4];
    const float* pin_emb     = (const float*)d_in[5];
    const float* seg_emb     = (const float*)d_in[6];
    const float* emb_ln_w    = (const float*)d_in[7];
    const float* emb_ln_b    = (const float*)d_in[8];
    const float* rel_emb     = (const float*)d_in[9];
    const float* Wq = (const float*)d_in[10]; const float* bq = (const float*)d_in[11];
    const float* Wk = (const float*)d_in[12]; const float* bk = (const float*)d_in[13];
    const float* Wv = (const float*)d_in[14]; const float* bv = (const float*)d_in[15];
    const float* Wo = (const float*)d_in[16]; const float* bo = (const float*)d_in[17];
    const float* ln1w = (const float*)d_in[18]; const float* ln1b = (const float*)d_in[19];
    const float* W1 = (const float*)d_in[20]; const float* b1 = (const float*)d_in[21];
    const float* W2 = (const float*)d_in[22]; const float* b2 = (const float*)d_in[23];
    const float* ln2w = (const float*)d_in[24]; const float* ln2b = (const float*)d_in[25];

    float *h, *q, *k, *v, *ctx, *tmp, *posk, *posq, *scores, *c2p, *p2c;
    int *c2pi, *p2ci;
    cudaGetSymbolAddress((void**)&h,      g_h);
    cudaGetSymbolAddress((void**)&q,      g_q);
    cudaGetSymbolAddress((void**)&k,      g_k);
    cudaGetSymbolAddress((void**)&v,      g_v);
    cudaGetSymbolAddress((void**)&ctx,    g_ctx);
    cudaGetSymbolAddress((void**)&tmp,    g_tmp);
    cudaGetSymbolAddress((void**)&posk,   g_posk);
    cudaGetSymbolAddress((void**)&posq,   g_posq);
    cudaGetSymbolAddress((void**)&scores, g_scores);
    cudaGetSymbolAddress((void**)&c2p,    g_c2p);
    cudaGetSymbolAddress((void**)&p2c,    g_p2c);
    cudaGetSymbolAddress((void**)&c2pi,   g_c2pi);
    cudaGetSymbolAddress((void**)&p2ci,   g_p2ci);

    const float scale = 0.07216878364870323f;  // 1/sqrt(3*DH)

    embed_ln_kernel<<<MM, 256>>>(input_ids, segment_ids, pinyin_ids, attn_mask,
                                 tok_emb, pin_emb, seg_emb, emb_ln_w, emb_ln_b, h);
    relpos_kernel<<<dim3(2, SS), 256>>>(c2pi, p2ci);

    for (int i = 0; i < LL; i++) {
        const float* Wq_i = Wq + (size_t)i * DD * DD; const float* bq_i = bq + (size_t)i * DD;
        const float* Wk_i = Wk + (size_t)i * DD * DD; const float* bk_i = bk + (size_t)i * DD;
        const float* Wv_i = Wv + (size_t)i * DD * DD; const float* bv_i = bv + (size_t)i * DD;
        const float* Wo_i = Wo + (size_t)i * DD * DD; const float* bo_i = bo + (size_t)i * DD;
        const float* W1_i = W1 + (size_t)i * DD * FF; const float* b1_i = b1 + (size_t)i * FF;
        const float* W2_i = W2 + (size_t)i * FF * DD; const float* b2_i = b2 + (size_t)i * DD;

        // QKV projections
        gemm_nn<<<dim3(DD / 128, MM / 128), 256>>>(h, Wq_i, bq_i, q, MM, DD, DD, 0);
        gemm_nn<<<dim3(DD / 128, MM / 128), 256>>>(h, Wk_i, bk_i, k, MM, DD, DD, 0);
        gemm_nn<<<dim3(DD / 128, MM / 128), 256>>>(h, Wv_i, bv_i, v, MM, DD, DD, 0);
        // positional projections (share content weights)
        gemm_nn<<<dim3(DD / 128, PP / 128), 256>>>(rel_emb, Wk_i, bk_i, posk, PP, DD, DD, 0);
        gemm_nn<<<dim3(DD / 128, PP / 128), 256>>>(rel_emb, Wq_i, bq_i, posq, PP, DD, DD, 0);

        // attention scores: Q·K^T, Q·posK^T (c2p), K·posQ^T (p2c), all pre-scaled
        score_gemm<<<dim3(8, 8, BH), 256>>>(q, k,    scores, 1, scale);
        score_gemm<<<dim3(8, 8, BH), 256>>>(q, posk, c2p,    0, scale);
        score_gemm<<<dim3(8, 8, BH), 256>>>(k, posq, p2c,    0, scale);

        softmax_gather<<<dim3(SS, BH), 256>>>(scores, c2p, p2c, c2pi, p2ci, attn_mask);

        ctx_gemm<<<dim3(8, BH), 256>>>(scores, v, ctx);

        // output projection + residual LN
        gemm_nn<<<dim3(DD / 128, MM / 128), 256>>>(ctx, Wo_i, bo_i, tmp, MM, DD, DD, 0);
        add_ln_kernel<<<MM, 256>>>(h, tmp, ln1w + (size_t)i * DD, ln1b + (size_t)i * DD);

        // feed-forward
        gemm_nn<<<dim3(FF / 128, MM / 128), 256>>>(h, W1_i, b1_i, tmp, MM, FF, DD, 1);
        gemm_nn<<<dim3(DD / 128, MM / 128), 256>>>(tmp, W2_i, b2_i, ctx, MM, DD, FF, 0);
        add_ln_kernel<<<MM, 256>>>(h, ctx, ln2w + (size_t)i * DD, ln2b + (size_t)i * DD);
    }

    cudaMemcpyAsync(d_out, h, sizeof(float) * (size_t)out_size, cudaMemcpyDeviceToDevice);
}

// round 2
// speedup vs baseline: 2.8435x; 2.8435x over previous
#include <cuda_runtime.h>
#include <cuda_bf16.h>
#include <math.h>

// ---------------- problem constants ----------------
#define BB 4
#define SS 512
#define DD 768
#define HH 12
#define LL 12
#define FF 3072
#define DH 64
#define PP 512        // rel-embedding rows (2*BUCKETS)
#define BH (BB*HH)    // 48
#define MM (BB*SS)    // 2048 tokens

// ---------------- device scratch ----------------
__device__ float g_h   [MM*DD];
__device__ float g_q   [MM*DD];
__device__ float g_k   [MM*DD];
__device__ float g_v   [MM*DD];
__device__ float g_ctx [MM*DD];
__device__ float g_tmp [MM*FF];
__device__ float g_posk[PP*DD];
__device__ float g_posq[PP*DD];
__device__ float g_scores[(size_t)BH*SS*SS];
__device__ float g_c2p   [(size_t)BH*SS*SS];
__device__ float g_p2c   [(size_t)BH*SS*SS];
__device__ float g_p2cT  [(size_t)BH*SS*SS];
__device__ int   g_c2pi[SS*SS];
__device__ int   g_p2ci[SS*SS];

// ---------------- tf32 helpers ----------------
__device__ __forceinline__ unsigned f2tf(float x) {
    unsigned u; asm("cvt.rna.tf32.f32 %0, %1;" : "=r"(u) : "f"(x)); return u;
}
__device__ __forceinline__ void mma_tf32(float* d, const unsigned* a, const unsigned* b) {
    asm volatile(
        "mma.sync.aligned.m16n8k8.row.col.f32.tf32.tf32.f32 "
        "{%0,%1,%2,%3}, {%4,%5,%6,%7}, {%8,%9}, {%0,%1,%2,%3};\n"
        : "+f"(d[0]), "+f"(d[1]), "+f"(d[2]), "+f"(d[3])
        : "r"(a[0]), "r"(a[1]), "r"(a[2]), "r"(a[3]), "r"(b[0]), "r"(b[1]));
}

// ---------------- embeddings + LayerNorm + mask ----------------
__global__ void __launch_bounds__(256) embed_ln_kernel(
    const int* __restrict__ ids, const int* __restrict__ segs, const int* __restrict__ pins,
    const float* __restrict__ mask,
    const float* __restrict__ tok, const float* __restrict__ pin, const float* __restrict__ seg,
    const float* __restrict__ w, const float* __restrict__ b, float* __restrict__ out)
{
    int t = blockIdx.x;
    int tid = threadIdx.x;
    __shared__ float xs[DD];
    __shared__ float red[256];

    size_t io = (size_t)ids[t]  * DD;
    size_t po = (size_t)pins[t] * DD;
    size_t so = (size_t)segs[t] * DD;

    float s = 0.f;
    for (int d = tid; d < DD; d += 256) {
        float x = tok[io + d] + pin[po + d] + seg[so + d];
        xs[d] = x; s += x;
    }
    red[tid] = s; __syncthreads();
    for (int st = 128; st > 0; st >>= 1) { if (tid < st) red[tid] += red[tid + st]; __syncthreads(); }
    float mu = red[0] * (1.0f / DD); __syncthreads();

    float s2 = 0.f;
    for (int d = tid; d < DD; d += 256) { float dv = xs[d] - mu; s2 += dv * dv; }
    red[tid] = s2; __syncthreads();
    for (int st = 128; st > 0; st >>= 1) { if (tid < st) red[tid] += red[tid + st]; __syncthreads(); }
    float inv = rsqrtf(red[0] * (1.0f / DD) + 1e-12f);

    float m = mask[t];
    for (int d = tid; d < DD; d += 256)
        out[(size_t)t * DD + d] = ((xs[d] - mu) * inv * w[d] + b[d]) * m;
}

// ---------------- relative-position bucketing ----------------
__global__ void relpos_kernel(int* __restrict__ c2pi, int* __restrict__ p2ci)
{
    int j = blockIdx.x * blockDim.x + threadIdx.x;
    int i = blockIdx.y;
    if (j >= SS) return;
    int rel = i - j;
    const int mid = 128;
    int ap = (rel < mid && rel > -mid) ? (mid - 1) : (rel < 0 ? -rel : rel);
    int bucket;
    if (ap <= mid) {
        bucket = rel;
    } else {
        double lp = ceil(log((double)ap / (double)mid) / log(511.0 / 128.0) * (mid - 1)) + mid;
        int sgn = (rel > 0) - (rel < 0);
        bucket = (int)lp * sgn;
    }
    int c = bucket + 256;  c = c < 0 ? 0 : (c > 511 ? 511 : c);
    int p = -bucket + 256; p = p < 0 ? 0 : (p > 511 ? 511 : p);
    c2pi[i * SS + j] = c;
    p2ci[i * SS + j] = p;
}

// ---------------- dense tf32 GEMM: C[M,N] = A*B + bias (+GELU), up to 3 fused B/C via z ----------------
// 128x128 tile, BK=16, 256 threads = 8 warps (2x4), warp tile 64x32 (4x4 mma tiles).
__global__ void __launch_bounds__(256) gemm_tf32(
    const float* __restrict__ A,
    const float* __restrict__ B0, const float* __restrict__ B1, const float* __restrict__ B2,
    const float* __restrict__ bi0, const float* __restrict__ bi1, const float* __restrict__ bi2,
    float* __restrict__ C0, float* __restrict__ C1, float* __restrict__ C2,
    int M, int N, int K, int act)
{
    const int z = blockIdx.z;
    const float* Bm   = (z == 0) ? B0  : (z == 1) ? B1  : B2;
    const float* bias = (z == 0) ? bi0 : (z == 1) ? bi1 : bi2;
    float*       C    = (z == 0) ? C0  : (z == 1) ? C1  : C2;

    __shared__ unsigned As[128 * 20];   // [m][k], stride 20 (20%32==20: frag LDS conflict-free)
    __shared__ unsigned Bs[16 * 136];   // [k][n], stride 136 (136%32==8: frag LDS conflict-free)

    int tid = threadIdx.x;
    int m0 = blockIdx.y * 128, n0 = blockIdx.x * 128;
    int w = tid >> 5, lane = tid & 31;
    int lr = lane >> 2, lc = lane & 3;
    int wm = (w >> 2) * 64, wn = (w & 3) * 32;

    int arow = tid >> 2, acol = (tid & 3) * 4;     // A: 2 rows per thread (arow, arow+64)
    int brow = tid >> 5, bcol = (tid & 31) * 4;    // B: 2 rows per thread (brow, brow+8)

    float acc[4][4][4] = {};

    for (int kt = 0; kt < K; kt += 16) {
        float4 a0 = *(const float4*)(A + (size_t)(m0 + arow) * K + kt + acol);
        float4 a1 = *(const float4*)(A + (size_t)(m0 + arow + 64) * K + kt + acol);
        float4 b0 = *(const float4*)(Bm + (size_t)(kt + brow) * N + n0 + bcol);
        float4 b1 = *(const float4*)(Bm + (size_t)(kt + brow + 8) * N + n0 + bcol);
        uint4 ua0 = make_uint4(f2tf(a0.x), f2tf(a0.y), f2tf(a0.z), f2tf(a0.w));
        uint4 ua1 = make_uint4(f2tf(a1.x), f2tf(a1.y), f2tf(a1.z), f2tf(a1.w));
        uint4 ub0 = make_uint4(f2tf(b0.x), f2tf(b0.y), f2tf(b0.z), f2tf(b0.w));
        uint4 ub1 = make_uint4(f2tf(b1.x), f2tf(b1.y), f2tf(b1.z), f2tf(b1.w));
        *(uint4*)(As + arow * 20 + acol)        = ua0;
        *(uint4*)(As + (arow + 64) * 20 + acol) = ua1;
        *(uint4*)(Bs + brow * 136 + bcol)       = ub0;
        *(uint4*)(Bs + (brow + 8) * 136 + bcol) = ub1;
        __syncthreads();

        #pragma unroll
        for (int ks = 0; ks < 16; ks += 8) {
            unsigned af[4][4], bf[4][2];
            #pragma unroll
            for (int mt = 0; mt < 4; mt++) {
                int m = wm + mt * 16 + lr;
                af[mt][0] = As[m * 20 + ks + lc];
                af[mt][1] = As[(m + 8) * 20 + ks + lc];
                af[mt][2] = As[m * 20 + ks + lc + 4];
                af[mt][3] = As[(m + 8) * 20 + ks + lc + 4];
            }
            #pragma unroll
            for (int nt = 0; nt < 4; nt++) {
                int n = wn + nt * 8 + lr;
                bf[nt][0] = Bs[(ks + lc) * 136 + n];
                bf[nt][1] = Bs[(ks + lc + 4) * 136 + n];
            }
            #pragma unroll
            for (int mt = 0; mt < 4; mt++)
                #pragma unroll
                for (int nt = 0; nt < 4; nt++)
                    mma_tf32(acc[mt][nt], af[mt], bf[nt]);
        }
        __syncthreads();
    }

    #pragma unroll
    for (int mt = 0; mt < 4; mt++) {
        int r = m0 + wm + mt * 16 + lr;
        #pragma unroll
        for (int nt = 0; nt < 4; nt++) {
            int c = n0 + wn + nt * 8 + lc * 2;
            float bv0 = bias[c], bv1 = bias[c + 1];
            float v00 = acc[mt][nt][0] + bv0, v01 = acc[mt][nt][1] + bv1;
            float v10 = acc[mt][nt][2] + bv0, v11 = acc[mt][nt][3] + bv1;
            if (act) {
                v00 = 0.5f * v00 * (1.0f + erff(v00 * 0.70710678118654752f));
                v01 = 0.5f * v01 * (1.0f + erff(v01 * 0.70710678118654752f));
                v10 = 0.5f * v10 * (1.0f + erff(v10 * 0.70710678118654752f));
                v11 = 0.5f * v11 * (1.0f + erff(v11 * 0.70710678118654752f));
            }
            *(float2*)(C + (size_t)r * N + c)       = make_float2(v00, v01);
            *(float2*)(C + (size_t)(r + 8) * N + c) = make_float2(v10, v11);
        }
    }
}

// ---------------- batched score GEMM (tf32): C[z,m,n] = scale * A[m,:]·B[n,:] ----------------
// A strided [.,DD] per row (head slice), B strided [.,DD]; both "row x k". 64x64 tile, K=DH.
__global__ void __launch_bounds__(128) score_tf32(
    const float* __restrict__ Ab, const float* __restrict__ Bb,
    float* __restrict__ Cb, int bBatch, float scale)
{
    int z = blockIdx.z; int b = z / HH, hh = z % HH;
    const float* A  = Ab + (size_t)b * SS * DD + hh * DH;
    const float* Bm = Bb + (bBatch ? (size_t)b * SS * DD : 0) + hh * DH;
    float* C = Cb + (size_t)z * SS * SS;
    int m0 = blockIdx.y * 64, n0 = blockIdx.x * 64;

    __shared__ unsigned As[64 * 20];   // [m][k]
    __shared__ unsigned Bs[64 * 20];   // [n][k]

    int tid = threadIdx.x;
    int w = tid >> 5, lane = tid & 31;
    int lr = lane >> 2, lc = lane & 3;
    int wm = (w >> 1) * 32, wn = (w & 1) * 32;

    int row = tid >> 2, col4 = (tid & 3) * 4;

    float acc[2][4][4] = {};

    for (int kt = 0; kt < DH; kt += 16) {
        float4 a0 = *(const float4*)(A + (size_t)(m0 + row) * DD + kt + col4);
        float4 a1 = *(const float4*)(A + (size_t)(m0 + row + 32) * DD + kt + col4);
        float4 b0 = *(const float4*)(Bm + (size_t)(n0 + row) * DD + kt + col4);
        float4 b1 = *(const float4*)(Bm + (size_t)(n0 + row + 32) * DD + kt + col4);
        *(uint4*)(As + row * 20 + col4)        = make_uint4(f2tf(a0.x), f2tf(a0.y), f2tf(a0.z), f2tf(a0.w));
        *(uint4*)(As + (row + 32) * 20 + col4) = make_uint4(f2tf(a1.x), f2tf(a1.y), f2tf(a1.z), f2tf(a1.w));
        *(uint4*)(Bs + row * 20 + col4)        = make_uint4(f2tf(b0.x), f2tf(b0.y), f2tf(b0.z), f2tf(b0.w));
        *(uint4*)(Bs + (row + 32) * 20 + col4) = make_uint4(f2tf(b1.x), f2tf(b1.y), f2tf(b1.z), f2tf(b1.w));
        __syncthreads();

        #pragma unroll
        for (int ks = 0; ks < 16; ks += 8) {
            unsigned af[2][4], bf[4][2];
            #pragma unroll
            for (int mt = 0; mt < 2; mt++) {
                int m = wm + mt * 16 + lr;
                af[mt][0] = As[m * 20 + ks + lc];
                af[mt][1] = As[(m + 8) * 20 + ks + lc];
                af[mt][2] = As[m * 20 + ks + lc + 4];
                af[mt][3] = As[(m + 8) * 20 + ks + lc + 4];
            }
            #pragma unroll
            for (int nt = 0; nt < 4; nt++) {
                int n = wn + nt * 8 + lr;
                bf[nt][0] = Bs[n * 20 + ks + lc];
                bf[nt][1] = Bs[n * 20 + ks + lc + 4];
            }
            #pragma unroll
            for (int mt = 0; mt < 2; mt++)
                #pragma unroll
                for (int nt = 0; nt < 4; nt++)
                    mma_tf32(acc[mt][nt], af[mt], bf[nt]);
        }
        __syncthreads();
    }

    #pragma unroll
    for (int mt = 0; mt < 2; mt++) {
        int r = m0 + wm + mt * 16 + lr;
        #pragma unroll
        for (int nt = 0; nt < 4; nt++) {
            int c = n0 + wn + nt * 8 + lc * 2;
            *(float2*)(C + (size_t)r * SS + c)       = make_float2(acc[mt][nt][0] * scale, acc[mt][nt][1] * scale);
            *(float2*)(C + (size_t)(r + 8) * SS + c) = make_float2(acc[mt][nt][2] * scale, acc[mt][nt][3] * scale);
        }
    }
}

// ---------------- p2c transpose-gather: p2cT[z,q,k] = p2c[z,k, p2ci[k,q]] ----------------
__global__ void __launch_bounds__(256) p2c_trans_kernel(
    const float* __restrict__ p2c, const int* __restrict__ p2ci, float* __restrict__ p2cT)
{
    int z = blockIdx.z;
    int q0 = blockIdx.x * 64, k0 = blockIdx.y * 64;
    __shared__ float tile[64][65];

    int tid = threadIdx.x;
    int ql = tid & 63, kb = tid >> 6;           // lanes along q -> coalesced gather reads
    #pragma unroll
    for (int i = 0; i < 16; i++) {
        int kl = kb + i * 4;
        int idx = p2ci[(k0 + kl) * SS + q0 + ql];
        tile[kl][ql] = p2c[((size_t)z * SS + k0 + kl) * SS + idx];
    }
    __syncthreads();
    int kl2 = tid & 63, qb = tid >> 6;          // lanes along k -> coalesced writes
    #pragma unroll
    for (int i = 0; i < 16; i++) {
        int ql2 = qb + i * 4;
        p2cT[((size_t)z * SS + q0 + ql2) * SS + k0 + kl2] = tile[kl2][ql2];
    }
}

// ---------------- fused c2p gather + p2cT add + mask + softmax ----------------
__global__ void __launch_bounds__(256) softmax_gather(
    float* __restrict__ scores, const float* __restrict__ c2p, const float* __restrict__ p2cT,
    const int* __restrict__ c2pi, const float* __restrict__ mask)
{
    int q = blockIdx.x, z = blockIdx.y;
    int b = z / HH;
    int t = threadIdx.x;
    float* srow = scores + ((size_t)z * SS + q) * SS;
    const float* crow = c2p + ((size_t)z * SS + q) * SS;
    const float* prow = p2cT + ((size_t)z * SS + q) * SS;

    float v[2];
    #pragma unroll
    for (int e = 0; e < 2; e++) {
        int k = t + e * 256;
        v[e] = srow[k] + crow[c2pi[q * SS + k]] + prow[k]
             + (1.0f - mask[b * SS + k]) * (-1e9f);
    }
    __shared__ float red[256];
    red[t] = fmaxf(v[0], v[1]); __syncthreads();
    for (int st = 128; st > 0; st >>= 1) { if (t < st) red[t] = fmaxf(red[t], red[t + st]); __syncthreads(); }
    float mx = red[0]; __syncthreads();
    float e0 = expf(v[0] - mx), e1 = expf(v[1] - mx);
    red[t] = e0 + e1; __syncthreads();
    for (int st = 128; st > 0; st >>= 1) { if (t < st) red[t] += red[t + st]; __syncthreads(); }
    float inv = 1.0f / red[0];
    srow[t]       = e0 * inv;
    srow[t + 256] = e1 * inv;
}

// ---------------- batched ctx GEMM (tf32): O[b,m,h,:] = P[z,m,:] * V[b,:,h,:] ----------------
__global__ void __launch_bounds__(128) ctx_tf32(
    const float* __restrict__ Pm, const float* __restrict__ V, float* __restrict__ O)
{
    int z = blockIdx.y; int b = z / HH, hh = z % HH;
    int m0 = blockIdx.x * 64;
    const float* A = Pm + (size_t)z * SS * SS;

    __shared__ unsigned As[64 * 20];   // [m][k]
    __shared__ unsigned Bs[16 * 72];   // [k][n], stride 72 (72%32==8)

    int tid = threadIdx.x;
    int w = tid >> 5, lane = tid & 31;
    int lr = lane >> 2, lc = lane & 3;
    int wm = (w >> 1) * 32, wn = (w & 1) * 32;

    int arow = tid >> 2, acol = (tid & 3) * 4;
    int brow = tid >> 4, bcol = (tid & 15) * 4;

    float acc[2][4][4] = {};

    for (int kt = 0; kt < SS; kt += 16) {
        float4 a0 = *(const float4*)(A + (size_t)(m0 + arow) * SS + kt + acol);
        float4 a1 = *(const float4*)(A + (size_t)(m0 + arow + 32) * SS + kt + acol);
        float4 b0 = *(const float4*)(V + ((size_t)b * SS + kt + brow) * DD + hh * DH + bcol);
        float4 b1 = *(const float4*)(V + ((size_t)b * SS + kt + brow + 8) * DD + hh * DH + bcol);
        *(uint4*)(As + arow * 20 + acol)        = make_uint4(f2tf(a0.x), f2tf(a0.y), f2tf(a0.z), f2tf(a0.w));
        *(uint4*)(As + (arow + 32) * 20 + acol) = make_uint4(f2tf(a1.x), f2tf(a1.y), f2tf(a1.z), f2tf(a1.w));
        *(uint4*)(Bs + brow * 72 + bcol)        = make_uint4(f2tf(b0.x), f2tf(b0.y), f2tf(b0.z), f2tf(b0.w));
        *(uint4*)(Bs + (brow + 8) * 72 + bcol)  = make_uint4(f2tf(b1.x), f2tf(b1.y), f2tf(b1.z), f2tf(b1.w));
        __syncthreads();

        #pragma unroll
        for (int ks = 0; ks < 16; ks += 8) {
            unsigned af[2][4], bf[4][2];
            #pragma unroll
            for (int mt = 0; mt < 2; mt++) {
                int m = wm + mt * 16 + lr;
                af[mt][0] = As[m * 20 + ks + lc];
                af[mt][1] = As[(m + 8) * 20 + ks + lc];
                af[mt][2] = As[m * 20 + ks + lc + 4];
                af[mt][3] = As[(m + 8) * 20 + ks + lc + 4];
            }
            #pragma unroll
            for (int nt = 0; nt < 4; nt++) {
                int n = wn + nt * 8 + lr;
                bf[nt][0] = Bs[(ks + lc) * 72 + n];
                bf[nt][1] = Bs[(ks + lc + 4) * 72 + n];
            }
            #pragma unroll
            for (int mt = 0; mt < 2; mt++)
                #pragma unroll
                for (int nt = 0; nt < 4; nt++)
                    mma_tf32(acc[mt][nt], af[mt], bf[nt]);
        }
        __syncthreads();
    }

    #pragma unroll
    for (int mt = 0; mt < 2; mt++) {
        int r = m0 + wm + mt * 16 + lr;
        #pragma unroll
        for (int nt = 0; nt < 4; nt++) {
            int c = wn + nt * 8 + lc * 2;
            *(float2*)(O + ((size_t)b * SS + r) * DD + hh * DH + c)     = make_float2(acc[mt][nt][0], acc[mt][nt][1]);
            *(float2*)(O + ((size_t)b * SS + r + 8) * DD + hh * DH + c) = make_float2(acc[mt][nt][2], acc[mt][nt][3]);
        }
    }
}

// ---------------- residual add + LayerNorm (in-place on h) ----------------
__global__ void __launch_bounds__(256) add_ln_kernel(
    float* __restrict__ h, const float* __restrict__ delta,
    const float* __restrict__ w, const float* __restrict__ b)
{
    int t = blockIdx.x;
    int tid = threadIdx.x;
    __shared__ float xs[DD];
    __shared__ float red[256];
    float* hr = h + (size_t)t * DD;
    const float* dr = delta + (size_t)t * DD;

    float s = 0.f;
    for (int d = tid; d < DD; d += 256) { float x = hr[d] + dr[d]; xs[d] = x; s += x; }
    red[tid] = s; __syncthreads();
    for (int st = 128; st > 0; st >>= 1) { if (tid < st) red[tid] += red[tid + st]; __syncthreads(); }
    float mu = red[0] * (1.0f / DD); __syncthreads();

    float s2 = 0.f;
    for (int d = tid; d < DD; d += 256) { float dv = xs[d] - mu; s2 += dv * dv; }
    red[tid] = s2; __syncthreads();
    for (int st = 128; st > 0; st >>= 1) { if (tid < st) red[tid] += red[tid + st]; __syncthreads(); }
    float inv = rsqrtf(red[0] * (1.0f / DD) + 1e-12f);

    for (int d = tid; d < DD; d += 256) hr[d] = (xs[d] - mu) * inv * w[d] + b[d];
}

// ---------------- host orchestration ----------------
extern "C" void kernel_launch(void* const* d_in, const int* in_sizes, int n_in,
                              void* d_out, int out_size)
{
    const int*   input_ids   = (const int*)  d_in[0];
    const int*   segment_ids = (const int*)  d_in[1];
    const int*   pinyin_ids  = (const int*)  d_in[2];
    const float* attn_mask   = (const float*)d_in[3];
    const float* tok_emb     = (const float*)d_in[4];
    const float* pin_emb     = (const float*)d_in[5];
    const float* seg_emb     = (const float*)d_in[6];
    const float* emb_ln_w    = (const float*)d_in[7];
    const float* emb_ln_b    = (const float*)d_in[8];
    const float* rel_emb     = (const float*)d_in[9];
    const float* Wq = (const float*)d_in[10]; const float* bq = (const float*)d_in[11];
    const float* Wk = (const float*)d_in[12]; const float* bk = (const float*)d_in[13];
    const float* Wv = (const float*)d_in[14]; const float* bv = (const float*)d_in[15];
    const float* Wo = (const float*)d_in[16]; const float* bo = (const float*)d_in[17];
    const float* ln1w = (const float*)d_in[18]; const float* ln1b = (const float*)d_in[19];
    const float* W1 = (const float*)d_in[20]; const float* b1 = (const float*)d_in[21];
    const float* W2 = (const float*)d_in[22]; const float* b2 = (const float*)d_in[23];
    const float* ln2w = (const float*)d_in[24]; const float* ln2b = (const float*)d_in[25];

    float *h, *q, *k, *v, *ctx, *tmp, *posk, *posq, *scores, *c2p, *p2c, *p2cT;
    int *c2pi, *p2ci;
    cudaGetSymbolAddress((void**)&h,      g_h);
    cudaGetSymbolAddress((void**)&q,      g_q);
    cudaGetSymbolAddress((void**)&k,      g_k);
    cudaGetSymbolAddress((void**)&v,      g_v);
    cudaGetSymbolAddress((void**)&ctx,    g_ctx);
    cudaGetSymbolAddress((void**)&tmp,    g_tmp);
    cudaGetSymbolAddress((void**)&posk,   g_posk);
    cudaGetSymbolAddress((void**)&posq,   g_posq);
    cudaGetSymbolAddress((void**)&scores, g_scores);
    cudaGetSymbolAddress((void**)&c2p,    g_c2p);
    cudaGetSymbolAddress((void**)&p2c,    g_p2c);
    cudaGetSymbolAddress((void**)&p2cT,   g_p2cT);
    cudaGetSymbolAddress((void**)&c2pi,   g_c2pi);
    cudaGetSymbolAddress((void**)&p2ci,   g_p2ci);

    const float scale = 0.07216878364870323f;  // 1/sqrt(3*DH)

    embed_ln_kernel<<<MM, 256>>>(input_ids, segment_ids, pinyin_ids, attn_mask,
                                 tok_emb, pin_emb, seg_emb, emb_ln_w, emb_ln_b, h);
    relpos_kernel<<<dim3(2, SS), 256>>>(c2pi, p2ci);

    for (int i = 0; i < LL; i++) {
        const float* Wq_i = Wq + (size_t)i * DD * DD; const float* bq_i = bq + (size_t)i * DD;
        const float* Wk_i = Wk + (size_t)i * DD * DD; const float* bk_i = bk + (size_t)i * DD;
        const float* Wv_i = Wv + (size_t)i * DD * DD; const float* bv_i = bv + (size_t)i * DD;
        const float* Wo_i = Wo + (size_t)i * DD * DD; const float* bo_i = bo + (size_t)i * DD;
        const float* W1_i = W1 + (size_t)i * DD * FF; const float* b1_i = b1 + (size_t)i * FF;
        const float* W2_i = W2 + (size_t)i * FF * DD; const float* b2_i = b2 + (size_t)i * DD;

        // fused QKV projections (z = 0/1/2)
        gemm_tf32<<<dim3(DD / 128, MM / 128, 3), 256>>>(
            h, Wq_i, Wk_i, Wv_i, bq_i, bk_i, bv_i, q, k, v, MM, DD, DD, 0);
        // fused positional projections (posk uses Wk, posq uses Wq)
        gemm_tf32<<<dim3(DD / 128, PP / 128, 2), 256>>>(
            rel_emb, Wk_i, Wq_i, Wq_i, bk_i, bq_i, bq_i, posk, posq, posq, PP, DD, DD, 0);

        // attention scores (pre-scaled)
        score_tf32<<<dim3(8, 8, BH), 128>>>(q, k,    scores, 1, scale);
        score_tf32<<<dim3(8, 8, BH), 128>>>(q, posk, c2p,    0, scale);
        score_tf32<<<dim3(8, 8, BH), 128>>>(k, posq, p2c,    0, scale);

        p2c_trans_kernel<<<dim3(8, 8, BH), 256>>>(p2c, p2ci, p2cT);
        softmax_gather<<<dim3(SS, BH), 256>>>(scores, c2p, p2cT, c2pi, attn_mask);

        ctx_tf32<<<dim3(8, BH), 128>>>(scores, v, ctx);

        // output projection + residual LN
        gemm_tf32<<<dim3(DD / 128, MM / 128, 1), 256>>>(
            ctx, Wo_i, Wo_i, Wo_i, bo_i, bo_i, bo_i, tmp, tmp, tmp, MM, DD, DD, 0);
        add_ln_kernel<<<MM, 256>>>(h, tmp, ln1w + (size_t)i * DD, ln1b + (size_t)i * DD);

        // feed-forward
        gemm_tf32<<<dim3(FF / 128, MM / 128, 1), 256>>>(
            h, W1_i, W1_i, W1_i, b1_i, b1_i, b1_i, tmp, tmp, tmp, MM, FF, DD, 1);
        gemm_tf32<<<dim3(DD / 128, MM / 128, 1), 256>>>(
            tmp, W2_i, W2_i, W2_i, b2_i, b2_i, b2_i, ctx, ctx, ctx, MM, DD, FF, 0);
        add_ln_kernel<<<MM, 256>>>(h, ctx, ln2w + (size_t)i * DD, ln2b + (size_t)i * DD);
    }

    cudaMemcpyAsync(d_out, h, sizeof(float) * (size_t)out_size, cudaMemcpyDeviceToDevice);
}

// round 3
// speedup vs baseline: 3.7735x; 1.3271x over previous
#include <cuda_runtime.h>
#include <cuda_bf16.h>
#include <math.h>

// ---------------- problem constants ----------------
#define BB 4
#define SS 512
#define DD 768
#define HH 12
#define LL 12
#define FF 3072
#define DH 64
#define PP 512
#define BH (BB*HH)    // 48
#define MM (BB*SS)    // 2048

// ---------------- device scratch ----------------
__device__ __align__(256) float g_h   [MM*DD];
__device__ __align__(256) float g_q   [MM*DD];
__device__ __align__(256) float g_k   [MM*DD];
__device__ __align__(256) float g_v   [MM*DD];
__device__ __align__(256) float g_ctx [MM*DD];
__device__ __align__(256) float g_tmp [MM*FF];
__device__ __align__(256) float g_posk[PP*DD];
__device__ __align__(256) float g_posq[PP*DD];
__device__ __align__(256) float g_scores[(size_t)BH*SS*SS];
__device__ int g_tab[1024];   // bucket table over d = q-k in [-511,511] (index d+511)

// ---------------- helpers ----------------
__device__ __forceinline__ unsigned f2tf(float x) {
    unsigned u; asm("cvt.rna.tf32.f32 %0, %1;" : "=r"(u) : "f"(x)); return u;
}
__device__ __forceinline__ void mma_tf32(float* d, const unsigned* a, const unsigned* b) {
    asm volatile(
        "mma.sync.aligned.m16n8k8.row.col.f32.tf32.tf32.f32 "
        "{%0,%1,%2,%3}, {%4,%5,%6,%7}, {%8,%9}, {%0,%1,%2,%3};\n"
        : "+f"(d[0]), "+f"(d[1]), "+f"(d[2]), "+f"(d[3])
        : "r"(a[0]), "r"(a[1]), "r"(a[2]), "r"(a[3]), "r"(b[0]), "r"(b[1]));
}
__device__ __forceinline__ void cp16(void* smem, const void* gmem) {
    unsigned sa = (unsigned)__cvta_generic_to_shared(smem);
    asm volatile("cp.async.cg.shared.global [%0], [%1], 16;" :: "r"(sa), "l"(gmem));
}
#define CP_COMMIT asm volatile("cp.async.commit_group;")
#define CP_WAIT2  asm volatile("cp.async.wait_group 2;")

// ---------------- embeddings + LayerNorm + mask ----------------
__global__ void __launch_bounds__(256) embed_ln_kernel(
    const int* __restrict__ ids, const int* __restrict__ segs, const int* __restrict__ pins,
    const float* __restrict__ mask,
    const float* __restrict__ tok, const float* __restrict__ pin, const float* __restrict__ seg,
    const float* __restrict__ w, const float* __restrict__ b, float* __restrict__ out)
{
    int t = blockIdx.x;
    int tid = threadIdx.x;
    __shared__ float xs[DD];
    __shared__ float red[256];

    size_t io = (size_t)ids[t]  * DD;
    size_t po = (size_t)pins[t] * DD;
    size_t so = (size_t)segs[t] * DD;

    float s = 0.f;
    for (int d = tid; d < DD; d += 256) {
        float x = tok[io + d] + pin[po + d] + seg[so + d];
        xs[d] = x; s += x;
    }
    red[tid] = s; __syncthreads();
    for (int st = 128; st > 0; st >>= 1) { if (tid < st) red[tid] += red[tid + st]; __syncthreads(); }
    float mu = red[0] * (1.0f / DD); __syncthreads();

    float s2 = 0.f;
    for (int d = tid; d < DD; d += 256) { float dv = xs[d] - mu; s2 += dv * dv; }
    red[tid] = s2; __syncthreads();
    for (int st = 128; st > 0; st >>= 1) { if (tid < st) red[tid] += red[tid + st]; __syncthreads(); }
    float inv = rsqrtf(red[0] * (1.0f / DD) + 1e-12f);

    float m = mask[t];
    for (int d = tid; d < DD; d += 256)
        out[(size_t)t * DD + d] = ((xs[d] - mu) * inv * w[d] + b[d]) * m;
}

// ---------------- bucket table: g_tab[d+511] = clip(bucket(d)+256, 0, 511) ----------------
__global__ void buckets_kernel(int* __restrict__ tab)
{
    int x = blockIdx.x * blockDim.x + threadIdx.x;
    if (x >= 1023) { if (x == 1023) tab[1023] = 0; return; }
    int rel = x - 511;
    const int mid = 128;
    int ap = (rel < mid && rel > -mid) ? (mid - 1) : (rel < 0 ? -rel : rel);
    int bucket;
    if (ap <= mid) {
        bucket = rel;
    } else {
        double lp = ceil(log((double)ap / (double)mid) / log(511.0 / 128.0) * (mid - 1)) + mid;
        int sgn = (rel > 0) - (rel < 0);
        bucket = (int)lp * sgn;
    }
    int c = bucket + 256; c = c < 0 ? 0 : (c > 511 ? 511 : c);
    tab[x] = c;
}

// ---------------- pipelined dense tf32 GEMM, up to 5 fused (B,bias,C) via z ----------------
// 128x128 tile, BK=16, 3-stage cp.async pipeline, 256 threads (8 warps 2x4), warp tile 64x32.
__global__ void __launch_bounds__(256) gemm_tf32(
    const float* __restrict__ Aa, const float* __restrict__ Ab, int Ma, int Mb,
    const float* __restrict__ B0, const float* __restrict__ B1, const float* __restrict__ B2,
    const float* __restrict__ B3, const float* __restrict__ B4,
    const float* __restrict__ bi0, const float* __restrict__ bi1, const float* __restrict__ bi2,
    const float* __restrict__ bi3, const float* __restrict__ bi4,
    float* __restrict__ C0, float* __restrict__ C1, float* __restrict__ C2,
    float* __restrict__ C3, float* __restrict__ C4,
    int N, int K, int act)
{
    const int z = blockIdx.z;
    const float* A = (z < 3) ? Aa : Ab;
    const int    M = (z < 3) ? Ma : Mb;
    int m0 = blockIdx.y * 128, n0 = blockIdx.x * 128;
    if (m0 >= M) return;
    const float* Bm   = (z == 0) ? B0  : (z == 1) ? B1  : (z == 2) ? B2  : (z == 3) ? B3  : B4;
    const float* bias = (z == 0) ? bi0 : (z == 1) ? bi1 : (z == 2) ? bi2 : (z == 3) ? bi3 : bi4;
    float*       C    = (z == 0) ? C0  : (z == 1) ? C1  : (z == 2) ? C2  : (z == 3) ? C3  : C4;

    extern __shared__ float dsm[];
    float* Asm = dsm;                 // 3 stages of 128*20
    float* Bsm = dsm + 3 * 128 * 20;  // 3 stages of 16*136

    int tid = threadIdx.x;
    int w = tid >> 5, lane = tid & 31;
    int lr = lane >> 2, lc = lane & 3;
    int wm = (w >> 2) * 64, wn = (w & 3) * 32;

    int arow = tid >> 2, acol = (tid & 3) * 4;
    int brow = tid >> 5, bcol = (tid & 31) * 4;

    const int kTiles = K >> 4;

    // cp.async tile loader
    #define ISSUE(sidx, kt) do { \
        float* as_ = Asm + (sidx) * 2560; \
        float* bs_ = Bsm + (sidx) * 2176; \
        const float* ap_ = A + (size_t)(m0 + arow) * K + (kt) * 16 + acol; \
        cp16(as_ + arow * 20 + acol, ap_); \
        cp16(as_ + (arow + 64) * 20 + acol, ap_ + (size_t)64 * K); \
        const float* bp_ = Bm + (size_t)((kt) * 16 + brow) * N + n0 + bcol; \
        cp16(bs_ + brow * 136 + bcol, bp_); \
        cp16(bs_ + (brow + 8) * 136 + bcol, bp_ + (size_t)8 * N); \
    } while (0)

    float acc[4][4][4] = {};

    ISSUE(0, 0); CP_COMMIT;
    ISSUE(1, 1); CP_COMMIT;

    for (int kt = 0; kt < kTiles; kt++) {
        int ld = kt + 2;
        if (ld < kTiles) ISSUE(ld % 3, ld);
        CP_COMMIT;
        CP_WAIT2;
        __syncthreads();

        const float* as = Asm + (kt % 3) * 2560;
        const float* bs = Bsm + (kt % 3) * 2176;

        #pragma unroll
        for (int ks = 0; ks < 16; ks += 8) {
            unsigned af[4][4], bf[4][2];
            #pragma unroll
            for (int mt = 0; mt < 4; mt++) {
                int m = wm + mt * 16 + lr;
                af[mt][0] = f2tf(as[m * 20 + ks + lc]);
                af[mt][1] = f2tf(as[(m + 8) * 20 + ks + lc]);
                af[mt][2] = f2tf(as[m * 20 + ks + lc + 4]);
                af[mt][3] = f2tf(as[(m + 8) * 20 + ks + lc + 4]);
            }
            #pragma unroll
            for (int nt = 0; nt < 4; nt++) {
                int n = wn + nt * 8 + lr;
                bf[nt][0] = f2tf(bs[(ks + lc) * 136 + n]);
                bf[nt][1] = f2tf(bs[(ks + lc + 4) * 136 + n]);
            }
            #pragma unroll
            for (int mt = 0; mt < 4; mt++)
                #pragma unroll
                for (int nt = 0; nt < 4; nt++)
                    mma_tf32(acc[mt][nt], af[mt], bf[nt]);
        }
        __syncthreads();
    }
    #undef ISSUE

    #pragma unroll
    for (int mt = 0; mt < 4; mt++) {
        int r = m0 + wm + mt * 16 + lr;
        #pragma unroll
        for (int nt = 0; nt < 4; nt++) {
            int c = n0 + wn + nt * 8 + lc * 2;
            float bv0 = bias[c], bv1 = bias[c + 1];
            float v00 = acc[mt][nt][0] + bv0, v01 = acc[mt][nt][1] + bv1;
            float v10 = acc[mt][nt][2] + bv0, v11 = acc[mt][nt][3] + bv1;
            if (act) {
                v00 = 0.5f * v00 * (1.0f + erff(v00 * 0.70710678118654752f));
                v01 = 0.5f * v01 * (1.0f + erff(v01 * 0.70710678118654752f));
                v10 = 0.5f * v10 * (1.0f + erff(v10 * 0.70710678118654752f));
                v11 = 0.5f * v11 * (1.0f + erff(v11 * 0.70710678118654752f));
            }
            *(float2*)(C + (size_t)r * N + c)       = make_float2(v00, v01);
            *(float2*)(C + (size_t)(r + 8) * N + c) = make_float2(v10, v11);
        }
    }
}

// ---------------- fused disentangled score kernel ----------------
// scores[z,q,k] = scale*( q·k + q·posk[g(q-k)] + k·posq[g(q-k)] ) + maskterm
// Per 64x64 tile: t = q_local - k_local + 63 in [0,126]; load 127 pos rows into smem.
__global__ void __launch_bounds__(256) score_fused(
    const float* __restrict__ Q, const float* __restrict__ Kt,
    const float* __restrict__ PKg, const float* __restrict__ PQg,
    const int* __restrict__ tab, const float* __restrict__ mask,
    float* __restrict__ scores, float scale)
{
    int z = blockIdx.z; int b = z / HH, hh = z % HH;
    int m0 = blockIdx.y * 64, n0 = blockIdx.x * 64;
    const float* Aq = Q  + (size_t)b * SS * DD + hh * DH;
    const float* Ak = Kt + (size_t)b * SS * DD + hh * DH;
    const float* PK = PKg + hh * DH;
    const float* PQ = PQg + hh * DH;

    extern __shared__ unsigned ssm[];
    unsigned* Qs  = ssm;              // 64 x 68
    unsigned* Ks  = ssm + 4352;       // 64 x 68
    unsigned* PKs = ssm + 8704;       // 128 x 68
    unsigned* PQs = ssm + 17408;      // 128 x 68
    float* C1s = (float*)(ssm + 8704);   // 64 x 132 (overlay, after MMA)
    float* C2s = (float*)(ssm + 17152);  // 64 x 132

    int tid = threadIdx.x;
    int w = tid >> 5, lane = tid & 31;
    int lr = lane >> 2, lc = lane & 3;
    int wr = w >> 2, wc = w & 3;     // warps 2 x 4

    const int dlo = m0 - n0 - 63;

    // ---- load phase: 64-row chunks, each thread: row=tid>>2, 16 floats ----
    {
        int row = tid >> 2;
        int col = (tid & 3) * 16;
        #pragma unroll
        for (int c4 = 0; c4 < 4; c4++) {
            float4 v = *(const float4*)(Aq + (size_t)(m0 + row) * DD + col + c4 * 4);
            *(uint4*)(Qs + row * 68 + col + c4 * 4) = make_uint4(f2tf(v.x), f2tf(v.y), f2tf(v.z), f2tf(v.w));
        }
        #pragma unroll
        for (int c4 = 0; c4 < 4; c4++) {
            float4 v = *(const float4*)(Ak + (size_t)(n0 + row) * DD + col + c4 * 4);
            *(uint4*)(Ks + row * 68 + col + c4 * 4) = make_uint4(f2tf(v.x), f2tf(v.y), f2tf(v.z), f2tf(v.w));
        }
        #pragma unroll
        for (int half = 0; half < 2; half++) {
            int t = row + half * 64;
            int tt = t < 127 ? t : 126;
            int pidx = tab[dlo + tt + 511];
            #pragma unroll
            for (int c4 = 0; c4 < 4; c4++) {
                float4 vk = *(const float4*)(PK + (size_t)pidx * DD + col + c4 * 4);
                *(uint4*)(PKs + t * 68 + col + c4 * 4) = make_uint4(f2tf(vk.x), f2tf(vk.y), f2tf(vk.z), f2tf(vk.w));
                float4 vq = *(const float4*)(PQ + (size_t)pidx * DD + col + c4 * 4);
                *(uint4*)(PQs + t * 68 + col + c4 * 4) = make_uint4(f2tf(vq.x), f2tf(vq.y), f2tf(vq.z), f2tf(vq.w));
            }
        }
    }
    __syncthreads();

    // ---- MMA phase ----
    // S: 64x64 (warp 32x16), C1 = Q*PK^T: 64x128 (warp 32x32), C2 = K*PQ^T: 64x128
    float accS[2][2][4] = {};
    float acc1[2][4][4] = {};
    float acc2[2][4][4] = {};

    #pragma unroll
    for (int ks = 0; ks < DH; ks += 8) {
        unsigned aq[2][4], ak[2][4];
        #pragma unroll
        for (int mt = 0; mt < 2; mt++) {
            int m = wr * 32 + mt * 16 + lr;
            aq[mt][0] = Qs[m * 68 + ks + lc];       aq[mt][1] = Qs[(m + 8) * 68 + ks + lc];
            aq[mt][2] = Qs[m * 68 + ks + lc + 4];   aq[mt][3] = Qs[(m + 8) * 68 + ks + lc + 4];
            ak[mt][0] = Ks[m * 68 + ks + lc];       ak[mt][1] = Ks[(m + 8) * 68 + ks + lc];
            ak[mt][2] = Ks[m * 68 + ks + lc + 4];   ak[mt][3] = Ks[(m + 8) * 68 + ks + lc + 4];
        }
        unsigned bS[2][2], b1[4][2], b2[4][2];
        #pragma unroll
        for (int nt = 0; nt < 2; nt++) {
            int n = wc * 16 + nt * 8 + lr;
            bS[nt][0] = Ks[n * 68 + ks + lc];
            bS[nt][1] = Ks[n * 68 + ks + lc + 4];
        }
        #pragma unroll
        for (int nt = 0; nt < 4; nt++) {
            int n = wc * 32 + nt * 8 + lr;
            b1[nt][0] = PKs[n * 68 + ks + lc];
            b1[nt][1] = PKs[n * 68 + ks + lc + 4];
            b2[nt][0] = PQs[n * 68 + ks + lc];
            b2[nt][1] = PQs[n * 68 + ks + lc + 4];
        }
        #pragma unroll
        for (int mt = 0; mt < 2; mt++) {
            #pragma unroll
            for (int nt = 0; nt < 2; nt++) mma_tf32(accS[mt][nt], aq[mt], bS[nt]);
            #pragma unroll
            for (int nt = 0; nt < 4; nt++) { mma_tf32(acc1[mt][nt], aq[mt], b1[nt]); mma_tf32(acc2[mt][nt], ak[mt], b2[nt]); }
        }
    }
    __syncthreads();   // PK/PQ dead only when ALL warps finished MMA

    // ---- write C1/C2 to smem overlay ----
    #pragma unroll
    for (int mt = 0; mt < 2; mt++) {
        int r = wr * 32 + mt * 16 + lr;
        #pragma unroll
        for (int nt = 0; nt < 4; nt++) {
            int c = wc * 32 + nt * 8 + lc * 2;
            C1s[r * 132 + c] = acc1[mt][nt][0]; C1s[r * 132 + c + 1] = acc1[mt][nt][1];
            C1s[(r + 8) * 132 + c] = acc1[mt][nt][2]; C1s[(r + 8) * 132 + c + 1] = acc1[mt][nt][3];
            C2s[r * 132 + c] = acc2[mt][nt][0]; C2s[r * 132 + c + 1] = acc2[mt][nt][1];
            C2s[(r + 8) * 132 + c] = acc2[mt][nt][2]; C2s[(r + 8) * 132 + c + 1] = acc2[mt][nt][3];
        }
    }
    __syncthreads();

    // ---- epilogue: S + gathered C1 + gathered C2, scale, mask, store ----
    #pragma unroll
    for (int mt = 0; mt < 2; mt++) {
        #pragma unroll
        for (int nt = 0; nt < 2; nt++) {
            int r = wr * 32 + mt * 16 + lr;
            int c0 = wc * 16 + nt * 8 + lc * 2;
            #pragma unroll
            for (int half = 0; half < 2; half++) {
                int rr = r + half * 8;
                float o[2];
                #pragma unroll
                for (int e = 0; e < 2; e++) {
                    int cc = c0 + e;
                    int t = rr - cc + 63;
                    float val = (accS[mt][nt][half * 2 + e] + C1s[rr * 132 + t] + C2s[cc * 132 + t]) * scale;
                    val += (1.0f - mask[b * SS + n0 + cc]) * (-1e9f);
                    o[e] = val;
                }
                *(float2*)(scores + ((size_t)z * SS + m0 + rr) * SS + n0 + c0) = make_float2(o[0], o[1]);
            }
        }
    }
}

// ---------------- row softmax (in-place) ----------------
__global__ void __launch_bounds__(256) softmax_kernel(float* __restrict__ scores)
{
    int q = blockIdx.x, z = blockIdx.y;
    int t = threadIdx.x;
    float* srow = scores + ((size_t)z * SS + q) * SS;

    float v0 = srow[t], v1 = srow[t + 256];
    __shared__ float red[256];
    red[t] = fmaxf(v0, v1); __syncthreads();
    for (int st = 128; st > 0; st >>= 1) { if (t < st) red[t] = fmaxf(red[t], red[t + st]); __syncthreads(); }
    float mx = red[0]; __syncthreads();
    float e0 = expf(v0 - mx), e1 = expf(v1 - mx);
    red[t] = e0 + e1; __syncthreads();
    for (int st = 128; st > 0; st >>= 1) { if (t < st) red[t] += red[t + st]; __syncthreads(); }
    float inv = 1.0f / red[0];
    srow[t] = e0 * inv;
    srow[t + 256] = e1 * inv;
}

// ---------------- batched ctx GEMM (tf32): O[b,m,h,:] = P[z,m,:] * V[b,:,h,:] ----------------
__global__ void __launch_bounds__(128) ctx_tf32(
    const float* __restrict__ Pm, const float* __restrict__ V, float* __restrict__ O)
{
    int z = blockIdx.y; int b = z / HH, hh = z % HH;
    int m0 = blockIdx.x * 64;
    const float* A = Pm + (size_t)z * SS * SS;

    __shared__ unsigned As[64 * 20];
    __shared__ unsigned Bs[16 * 72];

    int tid = threadIdx.x;
    int w = tid >> 5, lane = tid & 31;
    int lr = lane >> 2, lc = lane & 3;
    int wm = (w >> 1) * 32, wn = (w & 1) * 32;

    int arow = tid >> 2, acol = (tid & 3) * 4;
    int brow = tid >> 4, bcol = (tid & 15) * 4;

    float acc[2][4][4] = {};

    for (int kt = 0; kt < SS; kt += 16) {
        float4 a0 = *(const float4*)(A + (size_t)(m0 + arow) * SS + kt + acol);
        float4 a1 = *(const float4*)(A + (size_t)(m0 + arow + 32) * SS + kt + acol);
        float4 b0 = *(const float4*)(V + ((size_t)b * SS + kt + brow) * DD + hh * DH + bcol);
        float4 b1 = *(const float4*)(V + ((size_t)b * SS + kt + brow + 8) * DD + hh * DH + bcol);
        *(uint4*)(As + arow * 20 + acol)        = make_uint4(f2tf(a0.x), f2tf(a0.y), f2tf(a0.z), f2tf(a0.w));
        *(uint4*)(As + (arow + 32) * 20 + acol) = make_uint4(f2tf(a1.x), f2tf(a1.y), f2tf(a1.z), f2tf(a1.w));
        *(uint4*)(Bs + brow * 72 + bcol)        = make_uint4(f2tf(b0.x), f2tf(b0.y), f2tf(b0.z), f2tf(b0.w));
        *(uint4*)(Bs + (brow + 8) * 72 + bcol)  = make_uint4(f2tf(b1.x), f2tf(b1.y), f2tf(b1.z), f2tf(b1.w));
        __syncthreads();

        #pragma unroll
        for (int ks = 0; ks < 16; ks += 8) {
            unsigned af[2][4], bf[4][2];
            #pragma unroll
            for (int mt = 0; mt < 2; mt++) {
                int m = wm + mt * 16 + lr;
                af[mt][0] = As[m * 20 + ks + lc];
                af[mt][1] = As[(m + 8) * 20 + ks + lc];
                af[mt][2] = As[m * 20 + ks + lc + 4];
                af[mt][3] = As[(m + 8) * 20 + ks + lc + 4];
            }
            #pragma unroll
            for (int nt = 0; nt < 4; nt++) {
                int n = wn + nt * 8 + lr;
                bf[nt][0] = Bs[(ks + lc) * 72 + n];
                bf[nt][1] = Bs[(ks + lc + 4) * 72 + n];
            }
            #pragma unroll
            for (int mt = 0; mt < 2; mt++)
                #pragma unroll
                for (int nt = 0; nt < 4; nt++)
                    mma_tf32(acc[mt][nt], af[mt], bf[nt]);
        }
        __syncthreads();
    }

    #pragma unroll
    for (int mt = 0; mt < 2; mt++) {
        int r = m0 + wm + mt * 16 + lr;
        #pragma unroll
        for (int nt = 0; nt < 4; nt++) {
            int c = wn + nt * 8 + lc * 2;
            *(float2*)(O + ((size_t)b * SS + r) * DD + hh * DH + c)     = make_float2(acc[mt][nt][0], acc[mt][nt][1]);
            *(float2*)(O + ((size_t)b * SS + r + 8) * DD + hh * DH + c) = make_float2(acc[mt][nt][2], acc[mt][nt][3]);
        }
    }
}

// ---------------- residual add + LayerNorm (in-place on h) ----------------
__global__ void __launch_bounds__(256) add_ln_kernel(
    float* __restrict__ h, const float* __restrict__ delta,
    const float* __restrict__ w, const float* __restrict__ b)
{
    int t = blockIdx.x;
    int tid = threadIdx.x;
    __shared__ float xs[DD];
    __shared__ float red[256];
    float* hr = h + (size_t)t * DD;
    const float* dr = delta + (size_t)t * DD;

    float s = 0.f;
    for (int d = tid; d < DD; d += 256) { float x = hr[d] + dr[d]; xs[d] = x; s += x; }
    red[tid] = s; __syncthreads();
    for (int st = 128; st > 0; st >>= 1) { if (tid < st) red[tid] += red[tid + st]; __syncthreads(); }
    float mu = red[0] * (1.0f / DD); __syncthreads();

    float s2 = 0.f;
    for (int d = tid; d < DD; d += 256) { float dv = xs[d] - mu; s2 += dv * dv; }
    red[tid] = s2; __syncthreads();
    for (int st = 128; st > 0; st >>= 1) { if (tid < st) red[tid] += red[tid + st]; __syncthreads(); }
    float inv = rsqrtf(red[0] * (1.0f / DD) + 1e-12f);

    for (int d = tid; d < DD; d += 256) hr[d] = (xs[d] - mu) * inv * w[d] + b[d];
}

// ---------------- host orchestration ----------------
extern "C" void kernel_launch(void* const* d_in, const int* in_sizes, int n_in,
                              void* d_out, int out_size)
{
    const int*   input_ids   = (const int*)  d_in[0];
    const int*   segment_ids = (const int*)  d_in[1];
    const int*   pinyin_ids  = (const int*)  d_in[2];
    const float* attn_mask   = (const float*)d_in[3];
    const float* tok_emb     = (const float*)d_in[4];
    const float* pin_emb     = (const float*)d_in[5];
    const float* seg_emb     = (const float*)d_in[6];
    const float* emb_ln_w    = (const float*)d_in[7];
    const float* emb_ln_b    = (const float*)d_in[8];
    const float* rel_emb     = (const float*)d_in[9];
    const float* Wq = (const float*)d_in[10]; const float* bq = (const float*)d_in[11];
    const float* Wk = (const float*)d_in[12]; const float* bk = (const float*)d_in[13];
    const float* Wv = (const float*)d_in[14]; const float* bv = (const float*)d_in[15];
    const float* Wo = (const float*)d_in[16]; const float* bo = (const float*)d_in[17];
    const float* ln1w = (const float*)d_in[18]; const float* ln1b = (const float*)d_in[19];
    const float* W1 = (const float*)d_in[20]; const float* b1 = (const float*)d_in[21];
    const float* W2 = (const float*)d_in[22]; const float* b2 = (const float*)d_in[23];
    const float* ln2w = (const float*)d_in[24]; const float* ln2b = (const float*)d_in[25];

    float *h, *q, *k, *v, *ctx, *tmp, *posk, *posq, *scores;
    int *tab;
    cudaGetSymbolAddress((void**)&h,      g_h);
    cudaGetSymbolAddress((void**)&q,      g_q);
    cudaGetSymbolAddress((void**)&k,      g_k);
    cudaGetSymbolAddress((void**)&v,      g_v);
    cudaGetSymbolAddress((void**)&ctx,    g_ctx);
    cudaGetSymbolAddress((void**)&tmp,    g_tmp);
    cudaGetSymbolAddress((void**)&posk,   g_posk);
    cudaGetSymbolAddress((void**)&posq,   g_posq);
    cudaGetSymbolAddress((void**)&scores, g_scores);
    cudaGetSymbolAddress((void**)&tab,    g_tab);

    const int GEMM_SMEM  = 3 * (128 * 20 + 16 * 136) * 4;   // 56832
    const int SCORE_SMEM = (4352 * 2 + 8704 * 2) * 4;       // 104448
    cudaFuncSetAttribute(gemm_tf32,  cudaFuncAttributeMaxDynamicSharedMemorySize, GEMM_SMEM);
    cudaFuncSetAttribute(score_fused, cudaFuncAttributeMaxDynamicSharedMemorySize, SCORE_SMEM);

    const float scale = 0.07216878364870323f;  // 1/sqrt(3*DH)

    embed_ln_kernel<<<MM, 256>>>(input_ids, segment_ids, pinyin_ids, attn_mask,
                                 tok_emb, pin_emb, seg_emb, emb_ln_w, emb_ln_b, h);
    buckets_kernel<<<4, 256>>>(tab);

    for (int i = 0; i < LL; i++) {
        const float* Wq_i = Wq + (size_t)i * DD * DD; const float* bq_i = bq + (size_t)i * DD;
        const float* Wk_i = Wk + (size_t)i * DD * DD; const float* bk_i = bk + (size_t)i * DD;
        const float* Wv_i = Wv + (size_t)i * DD * DD; const float* bv_i = bv + (size_t)i * DD;
        const float* Wo_i = Wo + (size_t)i * DD * DD; const float* bo_i = bo + (size_t)i * DD;
        const float* W1_i = W1 + (size_t)i * DD * FF; const float* b1_i = b1 + (size_t)i * FF;
        const float* W2_i = W2 + (size_t)i * FF * DD; const float* b2_i = b2 + (size_t)i * DD;

        // QKV + posK + posQ fused (z = 0..4)
        gemm_tf32<<<dim3(DD / 128, MM / 128, 5), 256, GEMM_SMEM>>>(
            h, rel_emb, MM, PP,
            Wq_i, Wk_i, Wv_i, Wk_i, Wq_i,
            bq_i, bk_i, bv_i, bk_i, bq_i,
            q, k, v, posk, posq,
            DD, DD, 0);

        // fused disentangled scores (QK^T + c2p + p2c + mask), then softmax
        score_fused<<<dim3(8, 8, BH), 256, SCORE_SMEM>>>(q, k, posk, posq, tab, attn_mask, scores, scale);
        softmax_kernel<<<dim3(SS, BH), 256>>>(scores);

        ctx_tf32<<<dim3(8, BH), 128>>>(scores, v, ctx);

        // output projection + residual LN
        gemm_tf32<<<dim3(DD / 128, MM / 128, 1), 256, GEMM_SMEM>>>(
            ctx, ctx, MM, MM, Wo_i, Wo_i, Wo_i, Wo_i, Wo_i,
            bo_i, bo_i, bo_i, bo_i, bo_i, tmp, tmp, tmp, tmp, tmp, DD, DD, 0);
        add_ln_kernel<<<MM, 256>>>(h, tmp, ln1w + (size_t)i * DD, ln1b + (size_t)i * DD);

        // feed-forward
        gemm_tf32<<<dim3(FF / 128, MM / 128, 1), 256, GEMM_SMEM>>>(
            h, h, MM, MM, W1_i, W1_i, W1_i, W1_i, W1_i,
            b1_i, b1_i, b1_i, b1_i, b1_i, tmp, tmp, tmp, tmp, tmp, FF, DD, 1);
        gemm_tf32<<<dim3(DD / 128, MM / 128, 1), 256, GEMM_SMEM>>>(
            tmp, tmp, MM, MM, W2_i, W2_i, W2_i, W2_i, W2_i,
            b2_i, b2_i, b2_i, b2_i, b2_i, ctx, ctx, ctx, ctx, ctx, DD, FF, 0);
        add_ln_kernel<<<MM, 256>>>(h, ctx, ln2w + (size_t)i * DD, ln2b + (size_t)i * DD);
    }

    cudaMemcpyAsync(d_out, h, sizeof(float) * (size_t)out_size, cudaMemcpyDeviceToDevice);
}

// round 4
// speedup vs baseline: 4.1313x; 1.0948x over previous
#include <cuda_runtime.h>
#include <cuda_bf16.h>
#include <math.h>

// ---------------- problem constants ----------------
#define BB 4
#define SS 512
#define DD 768
#define HH 12
#define LL 12
#define FF 3072
#define DH 64
#define PP 512
#define BH (BB*HH)    // 48
#define MM (BB*SS)    // 2048

// ---------------- device scratch ----------------
__device__ __align__(256) float g_h   [MM*DD];
__device__ __align__(256) float g_q   [MM*DD];
__device__ __align__(256) float g_k   [MM*DD];
__device__ __align__(256) float g_v   [MM*DD];
__device__ __align__(256) float g_ctx [MM*DD];
__device__ __align__(256) float g_tmp [MM*FF];
__device__ __align__(256) float g_posk[PP*DD];
__device__ __align__(256) float g_posq[PP*DD];
__device__ __align__(256) float g_scores[(size_t)BH*SS*SS];
__device__ int g_tab[1024];

// ---------------- helpers ----------------
__device__ __forceinline__ unsigned f2tf(float x) {
    unsigned u; asm("cvt.rna.tf32.f32 %0, %1;" : "=r"(u) : "f"(x)); return u;
}
__device__ __forceinline__ void mma_tf32(float* d, const unsigned* a, const unsigned* b) {
    asm volatile(
        "mma.sync.aligned.m16n8k8.row.col.f32.tf32.tf32.f32 "
        "{%0,%1,%2,%3}, {%4,%5,%6,%7}, {%8,%9}, {%0,%1,%2,%3};\n"
        : "+f"(d[0]), "+f"(d[1]), "+f"(d[2]), "+f"(d[3])
        : "r"(a[0]), "r"(a[1]), "r"(a[2]), "r"(a[3]), "r"(b[0]), "r"(b[1]));
}
__device__ __forceinline__ void cp16(void* smem, const void* gmem) {
    unsigned sa = (unsigned)__cvta_generic_to_shared(smem);
    asm volatile("cp.async.cg.shared.global [%0], [%1], 16;" :: "r"(sa), "l"(gmem));
}
#define CP_COMMIT asm volatile("cp.async.commit_group;")
#define CP_WAIT2  asm volatile("cp.async.wait_group 2;")

// ---------------- embeddings + LayerNorm + mask ----------------
__global__ void __launch_bounds__(256) embed_ln_kernel(
    const int* __restrict__ ids, const int* __restrict__ segs, const int* __restrict__ pins,
    const float* __restrict__ mask,
    const float* __restrict__ tok, const float* __restrict__ pin, const float* __restrict__ seg,
    const float* __restrict__ w, const float* __restrict__ b, float* __restrict__ out)
{
    int t = blockIdx.x;
    int tid = threadIdx.x;
    __shared__ float xs[DD];
    __shared__ float red[256];

    size_t io = (size_t)ids[t]  * DD;
    size_t po = (size_t)pins[t] * DD;
    size_t so = (size_t)segs[t] * DD;

    float s = 0.f;
    for (int d = tid; d < DD; d += 256) {
        float x = tok[io + d] + pin[po + d] + seg[so + d];
        xs[d] = x; s += x;
    }
    red[tid] = s; __syncthreads();
    for (int st = 128; st > 0; st >>= 1) { if (tid < st) red[tid] += red[tid + st]; __syncthreads(); }
    float mu = red[0] * (1.0f / DD); __syncthreads();

    float s2 = 0.f;
    for (int d = tid; d < DD; d += 256) { float dv = xs[d] - mu; s2 += dv * dv; }
    red[tid] = s2; __syncthreads();
    for (int st = 128; st > 0; st >>= 1) { if (tid < st) red[tid] += red[tid + st]; __syncthreads(); }
    float inv = rsqrtf(red[0] * (1.0f / DD) + 1e-12f);

    float m = mask[t];
    for (int d = tid; d < DD; d += 256)
        out[(size_t)t * DD + d] = ((xs[d] - mu) * inv * w[d] + b[d]) * m;
}

// ---------------- bucket table ----------------
__global__ void buckets_kernel(int* __restrict__ tab)
{
    int x = blockIdx.x * blockDim.x + threadIdx.x;
    if (x >= 1023) { if (x == 1023) tab[1023] = 0; return; }
    int rel = x - 511;
    const int mid = 128;
    int ap = (rel < mid && rel > -mid) ? (mid - 1) : (rel < 0 ? -rel : rel);
    int bucket;
    if (ap <= mid) {
        bucket = rel;
    } else {
        double lp = ceil(log((double)ap / (double)mid) / log(511.0 / 128.0) * (mid - 1)) + mid;
        int sgn = (rel > 0) - (rel < 0);
        bucket = (int)lp * sgn;
    }
    int c = bucket + 256; c = c < 0 ? 0 : (c > 511 ? 511 : c);
    tab[x] = c;
}

// ---------------- pipelined dense tf32 GEMM, up to 5 fused (B,bias,C) via z ----------------
__global__ void __launch_bounds__(256) gemm_tf32(
    const float* __restrict__ Aa, const float* __restrict__ Ab, int Ma, int Mb,
    const float* __restrict__ B0, const float* __restrict__ B1, const float* __restrict__ B2,
    const float* __restrict__ B3, const float* __restrict__ B4,
    const float* __restrict__ bi0, const float* __restrict__ bi1, const float* __restrict__ bi2,
    const float* __restrict__ bi3, const float* __restrict__ bi4,
    float* __restrict__ C0, float* __restrict__ C1, float* __restrict__ C2,
    float* __restrict__ C3, float* __restrict__ C4,
    int N, int K, int act)
{
    const int z = blockIdx.z;
    const float* A = (z < 3) ? Aa : Ab;
    const int    M = (z < 3) ? Ma : Mb;
    int m0 = blockIdx.y * 128, n0 = blockIdx.x * 128;
    if (m0 >= M) return;
    const float* Bm   = (z == 0) ? B0  : (z == 1) ? B1  : (z == 2) ? B2  : (z == 3) ? B3  : B4;
    const float* bias = (z == 0) ? bi0 : (z == 1) ? bi1 : (z == 2) ? bi2 : (z == 3) ? bi3 : bi4;
    float*       C    = (z == 0) ? C0  : (z == 1) ? C1  : (z == 2) ? C2  : (z == 3) ? C3  : C4;

    extern __shared__ float dsm[];
    float* Asm = dsm;
    float* Bsm = dsm + 3 * 128 * 20;

    int tid = threadIdx.x;
    int w = tid >> 5, lane = tid & 31;
    int lr = lane >> 2, lc = lane & 3;
    int wm = (w >> 2) * 64, wn = (w & 3) * 32;

    int arow = tid >> 2, acol = (tid & 3) * 4;
    int brow = tid >> 5, bcol = (tid & 31) * 4;

    const int kTiles = K >> 4;

    #define ISSUE(sidx, kt) do { \
        float* as_ = Asm + (sidx) * 2560; \
        float* bs_ = Bsm + (sidx) * 2176; \
        const float* ap_ = A + (size_t)(m0 + arow) * K + (kt) * 16 + acol; \
        cp16(as_ + arow * 20 + acol, ap_); \
        cp16(as_ + (arow + 64) * 20 + acol, ap_ + (size_t)64 * K); \
        const float* bp_ = Bm + (size_t)((kt) * 16 + brow) * N + n0 + bcol; \
        cp16(bs_ + brow * 136 + bcol, bp_); \
        cp16(bs_ + (brow + 8) * 136 + bcol, bp_ + (size_t)8 * N); \
    } while (0)

    float acc[4][4][4] = {};

    ISSUE(0, 0); CP_COMMIT;
    ISSUE(1, 1); CP_COMMIT;

    for (int kt = 0; kt < kTiles; kt++) {
        int ld = kt + 2;
        if (ld < kTiles) ISSUE(ld % 3, ld);
        CP_COMMIT;
        CP_WAIT2;
        __syncthreads();

        const float* as = Asm + (kt % 3) * 2560;
        const float* bs = Bsm + (kt % 3) * 2176;

        #pragma unroll
        for (int ks = 0; ks < 16; ks += 8) {
            unsigned af[4][4], bf[4][2];
            #pragma unroll
            for (int mt = 0; mt < 4; mt++) {
                int m = wm + mt * 16 + lr;
                af[mt][0] = f2tf(as[m * 20 + ks + lc]);
                af[mt][1] = f2tf(as[(m + 8) * 20 + ks + lc]);
                af[mt][2] = f2tf(as[m * 20 + ks + lc + 4]);
                af[mt][3] = f2tf(as[(m + 8) * 20 + ks + lc + 4]);
            }
            #pragma unroll
            for (int nt = 0; nt < 4; nt++) {
                int n = wn + nt * 8 + lr;
                bf[nt][0] = f2tf(bs[(ks + lc) * 136 + n]);
                bf[nt][1] = f2tf(bs[(ks + lc + 4) * 136 + n]);
            }
            #pragma unroll
            for (int mt = 0; mt < 4; mt++)
                #pragma unroll
                for (int nt = 0; nt < 4; nt++)
                    mma_tf32(acc[mt][nt], af[mt], bf[nt]);
        }
        __syncthreads();
    }
    #undef ISSUE

    #pragma unroll
    for (int mt = 0; mt < 4; mt++) {
        int r = m0 + wm + mt * 16 + lr;
        #pragma unroll
        for (int nt = 0; nt < 4; nt++) {
            int c = n0 + wn + nt * 8 + lc * 2;
            float bv0 = bias[c], bv1 = bias[c + 1];
            float v00 = acc[mt][nt][0] + bv0, v01 = acc[mt][nt][1] + bv1;
            float v10 = acc[mt][nt][2] + bv0, v11 = acc[mt][nt][3] + bv1;
            if (act) {
                v00 = 0.5f * v00 * (1.0f + erff(v00 * 0.70710678118654752f));
                v01 = 0.5f * v01 * (1.0f + erff(v01 * 0.70710678118654752f));
                v10 = 0.5f * v10 * (1.0f + erff(v10 * 0.70710678118654752f));
                v11 = 0.5f * v11 * (1.0f + erff(v11 * 0.70710678118654752f));
            }
            *(float2*)(C + (size_t)r * N + c)       = make_float2(v00, v01);
            *(float2*)(C + (size_t)(r + 8) * N + c) = make_float2(v10, v11);
        }
    }
}

// ---------------- split-K=2 dense GEMM (deterministic): z=0 -> C0 (+bias), z=1 -> C1 ----------------
__global__ void __launch_bounds__(256) gemm_tf32_sk(
    const float* __restrict__ A, const float* __restrict__ Bm, const float* __restrict__ bias,
    float* __restrict__ C0, float* __restrict__ C1, int N, int K)
{
    const int z = blockIdx.z;
    const int kHalf = K >> 1;
    const int kStart = z * kHalf;
    float* C = z ? C1 : C0;
    int m0 = blockIdx.y * 128, n0 = blockIdx.x * 128;

    extern __shared__ float dsm[];
    float* Asm = dsm;
    float* Bsm = dsm + 3 * 128 * 20;

    int tid = threadIdx.x;
    int w = tid >> 5, lane = tid & 31;
    int lr = lane >> 2, lc = lane & 3;
    int wm = (w >> 2) * 64, wn = (w & 3) * 32;

    int arow = tid >> 2, acol = (tid & 3) * 4;
    int brow = tid >> 5, bcol = (tid & 31) * 4;

    const int kTiles = kHalf >> 4;

    #define ISSUE(sidx, kt) do { \
        float* as_ = Asm + (sidx) * 2560; \
        float* bs_ = Bsm + (sidx) * 2176; \
        const float* ap_ = A + (size_t)(m0 + arow) * K + kStart + (kt) * 16 + acol; \
        cp16(as_ + arow * 20 + acol, ap_); \
        cp16(as_ + (arow + 64) * 20 + acol, ap_ + (size_t)64 * K); \
        const float* bp_ = Bm + (size_t)(kStart + (kt) * 16 + brow) * N + n0 + bcol; \
        cp16(bs_ + brow * 136 + bcol, bp_); \
        cp16(bs_ + (brow + 8) * 136 + bcol, bp_ + (size_t)8 * N); \
    } while (0)

    float acc[4][4][4] = {};

    ISSUE(0, 0); CP_COMMIT;
    ISSUE(1, 1); CP_COMMIT;

    for (int kt = 0; kt < kTiles; kt++) {
        int ld = kt + 2;
        if (ld < kTiles) ISSUE(ld % 3, ld);
        CP_COMMIT;
        CP_WAIT2;
        __syncthreads();

        const float* as = Asm + (kt % 3) * 2560;
        const float* bs = Bsm + (kt % 3) * 2176;

        #pragma unroll
        for (int ks = 0; ks < 16; ks += 8) {
            unsigned af[4][4], bf[4][2];
            #pragma unroll
            for (int mt = 0; mt < 4; mt++) {
                int m = wm + mt * 16 + lr;
                af[mt][0] = f2tf(as[m * 20 + ks + lc]);
                af[mt][1] = f2tf(as[(m + 8) * 20 + ks + lc]);
                af[mt][2] = f2tf(as[m * 20 + ks + lc + 4]);
                af[mt][3] = f2tf(as[(m + 8) * 20 + ks + lc + 4]);
            }
            #pragma unroll
            for (int nt = 0; nt < 4; nt++) {
                int n = wn + nt * 8 + lr;
                bf[nt][0] = f2tf(bs[(ks + lc) * 136 + n]);
                bf[nt][1] = f2tf(bs[(ks + lc + 4) * 136 + n]);
            }
            #pragma unroll
            for (int mt = 0; mt < 4; mt++)
                #pragma unroll
                for (int nt = 0; nt < 4; nt++)
                    mma_tf32(acc[mt][nt], af[mt], bf[nt]);
        }
        __syncthreads();
    }
    #undef ISSUE

    #pragma unroll
    for (int mt = 0; mt < 4; mt++) {
        int r = m0 + wm + mt * 16 + lr;
        #pragma unroll
        for (int nt = 0; nt < 4; nt++) {
            int c = n0 + wn + nt * 8 + lc * 2;
            float bv0 = z ? 0.f : bias[c], bv1 = z ? 0.f : bias[c + 1];
            *(float2*)(C + (size_t)r * N + c)       = make_float2(acc[mt][nt][0] + bv0, acc[mt][nt][1] + bv1);
            *(float2*)(C + (size_t)(r + 8) * N + c) = make_float2(acc[mt][nt][2] + bv0, acc[mt][nt][3] + bv1);
        }
    }
}

// ---------------- fused disentangled score kernel ----------------
__global__ void __launch_bounds__(256) score_fused(
    const float* __restrict__ Q, const float* __restrict__ Kt,
    const float* __restrict__ PKg, const float* __restrict__ PQg,
    const int* __restrict__ tab, const float* __restrict__ mask,
    float* __restrict__ scores, float scale)
{
    int z = blockIdx.z; int b = z / HH, hh = z % HH;
    int m0 = blockIdx.y * 64, n0 = blockIdx.x * 64;
    const float* Aq = Q  + (size_t)b * SS * DD + hh * DH;
    const float* Ak = Kt + (size_t)b * SS * DD + hh * DH;
    const float* PK = PKg + hh * DH;
    const float* PQ = PQg + hh * DH;

    extern __shared__ unsigned ssm[];
    unsigned* Qs  = ssm;              // 64 x 68
    unsigned* Ks  = ssm + 4352;       // 64 x 68
    unsigned* PKs = ssm + 8704;       // 128 x 68
    unsigned* PQs = ssm + 17408;      // 128 x 68
    float* C1s = (float*)(ssm + 8704);   // 64 x 132 overlay
    float* C2s = (float*)(ssm + 17152);  // 64 x 132

    int tid = threadIdx.x;
    int w = tid >> 5, lane = tid & 31;
    int lr = lane >> 2, lc = lane & 3;
    int wr = w >> 2, wc = w & 3;

    const int dlo = m0 - n0 - 63;

    {
        int row = tid >> 2;
        int col = (tid & 3) * 16;
        #pragma unroll
        for (int c4 = 0; c4 < 4; c4++) {
            float4 v = *(const float4*)(Aq + (size_t)(m0 + row) * DD + col + c4 * 4);
            *(uint4*)(Qs + row * 68 + col + c4 * 4) = make_uint4(f2tf(v.x), f2tf(v.y), f2tf(v.z), f2tf(v.w));
        }
        #pragma unroll
        for (int c4 = 0; c4 < 4; c4++) {
            float4 v = *(const float4*)(Ak + (size_t)(n0 + row) * DD + col + c4 * 4);
            *(uint4*)(Ks + row * 68 + col + c4 * 4) = make_uint4(f2tf(v.x), f2tf(v.y), f2tf(v.z), f2tf(v.w));
        }
        #pragma unroll
        for (int half = 0; half < 2; half++) {
            int t = row + half * 64;
            int tt = t < 127 ? t : 126;
            int pidx = tab[dlo + tt + 511];
            #pragma unroll
            for (int c4 = 0; c4 < 4; c4++) {
                float4 vk = *(const float4*)(PK + (size_t)pidx * DD + col + c4 * 4);
                *(uint4*)(PKs + t * 68 + col + c4 * 4) = make_uint4(f2tf(vk.x), f2tf(vk.y), f2tf(vk.z), f2tf(vk.w));
                float4 vq = *(const float4*)(PQ + (size_t)pidx * DD + col + c4 * 4);
                *(uint4*)(PQs + t * 68 + col + c4 * 4) = make_uint4(f2tf(vq.x), f2tf(vq.y), f2tf(vq.z), f2tf(vq.w));
            }
        }
    }
    __syncthreads();

    float accS[2][2][4] = {};
    float acc1[2][4][4] = {};
    float acc2[2][4][4] = {};

    #pragma unroll
    for (int ks = 0; ks < DH; ks += 8) {
        unsigned aq[2][4], ak[2][4];
        #pragma unroll
        for (int mt = 0; mt < 2; mt++) {
            int m = wr * 32 + mt * 16 + lr;
            aq[mt][0] = Qs[m * 68 + ks + lc];       aq[mt][1] = Qs[(m + 8) * 68 + ks + lc];
            aq[mt][2] = Qs[m * 68 + ks + lc + 4];   aq[mt][3] = Qs[(m + 8) * 68 + ks + lc + 4];
            ak[mt][0] = Ks[m * 68 + ks + lc];       ak[mt][1] = Ks[(m + 8) * 68 + ks + lc];
            ak[mt][2] = Ks[m * 68 + ks + lc + 4];   ak[mt][3] = Ks[(m + 8) * 68 + ks + lc + 4];
        }
        unsigned bS[2][2], b1[4][2], b2[4][2];
        #pragma unroll
        for (int nt = 0; nt < 2; nt++) {
            int n = wc * 16 + nt * 8 + lr;
            bS[nt][0] = Ks[n * 68 + ks + lc];
            bS[nt][1] = Ks[n * 68 + ks + lc + 4];
        }
        #pragma unroll
        for (int nt = 0; nt < 4; nt++) {
            int n = wc * 32 + nt * 8 + lr;
            b1[nt][0] = PKs[n * 68 + ks + lc];
            b1[nt][1] = PKs[n * 68 + ks + lc + 4];
            b2[nt][0] = PQs[n * 68 + ks + lc];
            b2[nt][1] = PQs[n * 68 + ks + lc + 4];
        }
        #pragma unroll
        for (int mt = 0; mt < 2; mt++) {
            #pragma unroll
            for (int nt = 0; nt < 2; nt++) mma_tf32(accS[mt][nt], aq[mt], bS[nt]);
            #pragma unroll
            for (int nt = 0; nt < 4; nt++) { mma_tf32(acc1[mt][nt], aq[mt], b1[nt]); mma_tf32(acc2[mt][nt], ak[mt], b2[nt]); }
        }
    }
    __syncthreads();

    #pragma unroll
    for (int mt = 0; mt < 2; mt++) {
        int r = wr * 32 + mt * 16 + lr;
        #pragma unroll
        for (int nt = 0; nt < 4; nt++) {
            int c = wc * 32 + nt * 8 + lc * 2;
            C1s[r * 132 + c] = acc1[mt][nt][0]; C1s[r * 132 + c + 1] = acc1[mt][nt][1];
            C1s[(r + 8) * 132 + c] = acc1[mt][nt][2]; C1s[(r + 8) * 132 + c + 1] = acc1[mt][nt][3];
            C2s[r * 132 + c] = acc2[mt][nt][0]; C2s[r * 132 + c + 1] = acc2[mt][nt][1];
            C2s[(r + 8) * 132 + c] = acc2[mt][nt][2]; C2s[(r + 8) * 132 + c + 1] = acc2[mt][nt][3];
        }
    }
    __syncthreads();

    #pragma unroll
    for (int mt = 0; mt < 2; mt++) {
        #pragma unroll
        for (int nt = 0; nt < 2; nt++) {
            int r = wr * 32 + mt * 16 + lr;
            int c0 = wc * 16 + nt * 8 + lc * 2;
            #pragma unroll
            for (int half = 0; half < 2; half++) {
                int rr = r + half * 8;
                float o[2];
                #pragma unroll
                for (int e = 0; e < 2; e++) {
                    int cc = c0 + e;
                    int t = rr - cc + 63;
                    float val = (accS[mt][nt][half * 2 + e] + C1s[rr * 132 + t] + C2s[cc * 132 + t]) * scale;
                    val += (1.0f - mask[b * SS + n0 + cc]) * (-1e9f);
                    o[e] = val;
                }
                *(float2*)(scores + ((size_t)z * SS + m0 + rr) * SS + n0 + c0) = make_float2(o[0], o[1]);
            }
        }
    }
}

// ---------------- row softmax (float4, 128 threads/row) ----------------
__global__ void __launch_bounds__(128) softmax_kernel(float* __restrict__ scores)
{
    int q = blockIdx.x, z = blockIdx.y;
    int t = threadIdx.x;
    int lane = t & 31, wp = t >> 5;
    float4* row = (float4*)(scores + ((size_t)z * SS + q) * SS);

    float4 v = row[t];
    float mx = fmaxf(fmaxf(v.x, v.y), fmaxf(v.z, v.w));
    #pragma unroll
    for (int o = 16; o > 0; o >>= 1) mx = fmaxf(mx, __shfl_xor_sync(0xffffffffu, mx, o));
    __shared__ float sm[4];
    if (lane == 0) sm[wp] = mx;
    __syncthreads();
    mx = fmaxf(fmaxf(sm[0], sm[1]), fmaxf(sm[2], sm[3]));

    float4 e = make_float4(expf(v.x - mx), expf(v.y - mx), expf(v.z - mx), expf(v.w - mx));
    float s = e.x + e.y + e.z + e.w;
    #pragma unroll
    for (int o = 16; o > 0; o >>= 1) s += __shfl_xor_sync(0xffffffffu, s, o);
    __shared__ float sm2[4];
    if (lane == 0) sm2[wp] = s;
    __syncthreads();
    float inv = 1.0f / (sm2[0] + sm2[1] + sm2[2] + sm2[3]);
    row[t] = make_float4(e.x * inv, e.y * inv, e.z * inv, e.w * inv);
}

// ---------------- pipelined batched ctx GEMM: O[b,m,h,:] = P[z,m,:] * V[b,:,h,:] ----------------
// 128(m) x 64(n=DH) tile, BK=16, 3-stage cp.async, 256 threads (8 warps 4x2), warp 32x32.
__global__ void __launch_bounds__(256) ctx_tf32(
    const float* __restrict__ Pm, const float* __restrict__ V, float* __restrict__ O)
{
    int z = blockIdx.y; int b = z / HH, hh = z % HH;
    int m0 = blockIdx.x * 128;
    const float* A = Pm + (size_t)z * SS * SS;
    const float* Bv = V + (size_t)b * SS * DD + hh * DH;

    extern __shared__ float dsm[];
    float* Asm = dsm;                // 3 x (128*20)
    float* Bsm = dsm + 3 * 2560;     // 3 x (16*72)

    int tid = threadIdx.x;
    int w = tid >> 5, lane = tid & 31;
    int lr = lane >> 2, lc = lane & 3;
    int wm = (w >> 1) * 32, wn = (w & 1) * 32;

    int arow = tid & 127, acol = (tid >> 7) * 8;
    int brow = tid >> 4, bcol = (tid & 15) * 4;

    const int kTiles = SS / 16;   // 32

    #define ISSUE(sidx, kt) do { \
        float* as_ = Asm + (sidx) * 2560; \
        float* bs_ = Bsm + (sidx) * 1152; \
        const float* ap_ = A + (size_t)(m0 + arow) * SS + (kt) * 16 + acol; \
        cp16(as_ + arow * 20 + acol, ap_); \
        cp16(as_ + arow * 20 + acol + 4, ap_ + 4); \
        const float* bp_ = Bv + (size_t)((kt) * 16 + brow) * DD + bcol; \
        cp16(bs_ + brow * 72 + bcol, bp_); \
    } while (0)

    float acc[2][4][4] = {};

    ISSUE(0, 0); CP_COMMIT;
    ISSUE(1, 1); CP_COMMIT;

    for (int kt = 0; kt < kTiles; kt++) {
        int ld = kt + 2;
        if (ld < kTiles) ISSUE(ld % 3, ld);
        CP_COMMIT;
        CP_WAIT2;
        __syncthreads();

        const float* as = Asm + (kt % 3) * 2560;
        const float* bs = Bsm + (kt % 3) * 1152;

        #pragma unroll
        for (int ks = 0; ks < 16; ks += 8) {
            unsigned af[2][4], bf[4][2];
            #pragma unroll
            for (int mt = 0; mt < 2; mt++) {
                int m = wm + mt * 16 + lr;
                af[mt][0] = f2tf(as[m * 20 + ks + lc]);
                af[mt][1] = f2tf(as[(m + 8) * 20 + ks + lc]);
                af[mt][2] = f2tf(as[m * 20 + ks + lc + 4]);
                af[mt][3] = f2tf(as[(m + 8) * 20 + ks + lc + 4]);
            }
            #pragma unroll
            for (int nt = 0; nt < 4; nt++) {
                int n = wn + nt * 8 + lr;
                bf[nt][0] = f2tf(bs[(ks + lc) * 72 + n]);
                bf[nt][1] = f2tf(bs[(ks + lc + 4) * 72 + n]);
            }
            #pragma unroll
            for (int mt = 0; mt < 2; mt++)
                #pragma unroll
                for (int nt = 0; nt < 4; nt++)
                    mma_tf32(acc[mt][nt], af[mt], bf[nt]);
        }
        __syncthreads();
    }
    #undef ISSUE

    #pragma unroll
    for (int mt = 0; mt < 2; mt++) {
        int r = m0 + wm + mt * 16 + lr;
        #pragma unroll
        for (int nt = 0; nt < 4; nt++) {
            int c = wn + nt * 8 + lc * 2;
            *(float2*)(O + ((size_t)b * SS + r) * DD + hh * DH + c)     = make_float2(acc[mt][nt][0], acc[mt][nt][1]);
            *(float2*)(O + ((size_t)b * SS + r + 8) * DD + hh * DH + c) = make_float2(acc[mt][nt][2], acc[mt][nt][3]);
        }
    }
}

// ---------------- residual add (two deltas) + LayerNorm (in-place on h) ----------------
__global__ void __launch_bounds__(256) add_ln3_kernel(
    float* __restrict__ h, const float* __restrict__ d1, const float* __restrict__ d2,
    const float* __restrict__ w, const float* __restrict__ b)
{
    int t = blockIdx.x;
    int tid = threadIdx.x;
    __shared__ float xs[DD];
    __shared__ float red[256];
    float* hr = h + (size_t)t * DD;
    const float* r1 = d1 + (size_t)t * DD;
    const float* r2 = d2 + (size_t)t * DD;

    float s = 0.f;
    for (int d = tid; d < DD; d += 256) { float x = hr[d] + r1[d] + r2[d]; xs[d] = x; s += x; }
    red[tid] = s; __syncthreads();
    for (int st = 128; st > 0; st >>= 1) { if (tid < st) red[tid] += red[tid + st]; __syncthreads(); }
    float mu = red[0] * (1.0f / DD); __syncthreads();

    float s2 = 0.f;
    for (int d = tid; d < DD; d += 256) { float dv = xs[d] - mu; s2 += dv * dv; }
    red[tid] = s2; __syncthreads();
    for (int st = 128; st > 0; st >>= 1) { if (tid < st) red[tid] += red[tid + st]; __syncthreads(); }
    float inv = rsqrtf(red[0] * (1.0f / DD) + 1e-12f);

    for (int d = tid; d < DD; d += 256) hr[d] = (xs[d] - mu) * inv * w[d] + b[d];
}

// ---------------- host orchestration ----------------
extern "C" void kernel_launch(void* const* d_in, const int* in_sizes, int n_in,
                              void* d_out, int out_size)
{
    const int*   input_ids   = (const int*)  d_in[0];
    const int*   segment_ids = (const int*)  d_in[1];
    const int*   pinyin_ids  = (const int*)  d_in[2];
    const float* attn_mask   = (const float*)d_in[3];
    const float* tok_emb     = (const float*)d_in[4];
    const float* pin_emb     = (const float*)d_in[5];
    const float* seg_emb     = (const float*)d_in[6];
    const float* emb_ln_w    = (const float*)d_in[7];
    const float* emb_ln_b    = (const float*)d_in[8];
    const float* rel_emb     = (const float*)d_in[9];
    const float* Wq = (const float*)d_in[10]; const float* bq = (const float*)d_in[11];
    const float* Wk = (const float*)d_in[12]; const float* bk = (const float*)d_in[13];
    const float* Wv = (const float*)d_in[14]; const float* bv = (const float*)d_in[15];
    const float* Wo = (const float*)d_in[16]; const float* bo = (const float*)d_in[17];
    const float* ln1w = (const float*)d_in[18]; const float* ln1b = (const float*)d_in[19];
    const float* W1 = (const float*)d_in[20]; const float* b1 = (const float*)d_in[21];
    const float* W2 = (const float*)d_in[22]; const float* b2 = (const float*)d_in[23];
    const float* ln2w = (const float*)d_in[24]; const float* ln2b = (const float*)d_in[25];

    float *h, *q, *k, *v, *ctx, *tmp, *posk, *posq, *scores;
    int *tab;
    cudaGetSymbolAddress((void**)&h,      g_h);
    cudaGetSymbolAddress((void**)&q,      g_q);
    cudaGetSymbolAddress((void**)&k,      g_k);
    cudaGetSymbolAddress((void**)&v,      g_v);
    cudaGetSymbolAddress((void**)&ctx,    g_ctx);
    cudaGetSymbolAddress((void**)&tmp,    g_tmp);
    cudaGetSymbolAddress((void**)&posk,   g_posk);
    cudaGetSymbolAddress((void**)&posq,   g_posq);
    cudaGetSymbolAddress((void**)&scores, g_scores);
    cudaGetSymbolAddress((void**)&tab,    g_tab);

    const int GEMM_SMEM  = 3 * (128 * 20 + 16 * 136) * 4;   // 56832
    const int CTX_SMEM   = 3 * (128 * 20 + 16 * 72) * 4;    // 44544
    const int SCORE_SMEM = (4352 * 2 + 8704 * 2) * 4;       // 104448
    cudaFuncSetAttribute(gemm_tf32,    cudaFuncAttributeMaxDynamicSharedMemorySize, GEMM_SMEM);
    cudaFuncSetAttribute(gemm_tf32_sk, cudaFuncAttributeMaxDynamicSharedMemorySize, GEMM_SMEM);
    cudaFuncSetAttribute(ctx_tf32,     cudaFuncAttributeMaxDynamicSharedMemorySize, CTX_SMEM);
    cudaFuncSetAttribute(score_fused,  cudaFuncAttributeMaxDynamicSharedMemorySize, SCORE_SMEM);

    const float scale = 0.07216878364870323f;  // 1/sqrt(3*DH)

    embed_ln_kernel<<<MM, 256>>>(input_ids, segment_ids, pinyin_ids, attn_mask,
                                 tok_emb, pin_emb, seg_emb, emb_ln_w, emb_ln_b, h);
    buckets_kernel<<<4, 256>>>(tab);

    for (int i = 0; i < LL; i++) {
        const float* Wq_i = Wq + (size_t)i * DD * DD; const float* bq_i = bq + (size_t)i * DD;
        const float* Wk_i = Wk + (size_t)i * DD * DD; const float* bk_i = bk + (size_t)i * DD;
        const float* Wv_i = Wv + (size_t)i * DD * DD; const float* bv_i = bv + (size_t)i * DD;
        const float* Wo_i = Wo + (size_t)i * DD * DD; const float* bo_i = bo + (size_t)i * DD;
        const float* W1_i = W1 + (size_t)i * DD * FF; const float* b1_i = b1 + (size_t)i * FF;
        const float* W2_i = W2 + (size_t)i * FF * DD; const float* b2_i = b2 + (size_t)i * DD;

        // QKV + posK + posQ fused (z = 0..4)
        gemm_tf32<<<dim3(DD / 128, MM / 128, 5), 256, GEMM_SMEM>>>(
            h, rel_emb, MM, PP,
            Wq_i, Wk_i, Wv_i, Wk_i, Wq_i,
            bq_i, bk_i, bv_i, bk_i, bq_i,
            q, k, v, posk, posq,
            DD, DD, 0);

        // fused disentangled scores + softmax
        score_fused<<<dim3(8, 8, BH), 256, SCORE_SMEM>>>(q, k, posk, posq, tab, attn_mask, scores, scale);
        softmax_kernel<<<dim3(SS, BH), 128>>>(scores);

        // probs @ V  (q, k scratch now free)
        ctx_tf32<<<dim3(SS / 128, BH), 256, CTX_SMEM>>>(scores, v, ctx);

        // output projection (split-K=2 -> tmp, q) + residual LN
        gemm_tf32_sk<<<dim3(DD / 128, MM / 128, 2), 256, GEMM_SMEM>>>(
            ctx, Wo_i, bo_i, tmp, q, DD, DD);
        add_ln3_kernel<<<MM, 256>>>(h, tmp, q, ln1w + (size_t)i * DD, ln1b + (size_t)i * DD);

        // feed-forward: FF1 full, FF2 split-K=2 (-> ctx, k)
        gemm_tf32<<<dim3(FF / 128, MM / 128, 1), 256, GEMM_SMEM>>>(
            h, h, MM, MM, W1_i, W1_i, W1_i, W1_i, W1_i,
            b1_i, b1_i, b1_i, b1_i, b1_i, tmp, tmp, tmp, tmp, tmp, FF, DD, 1);
        gemm_tf32_sk<<<dim3(DD / 128, MM / 128, 2), 256, GEMM_SMEM>>>(
            tmp, W2_i, b2_i, ctx, k, DD, FF);
        add_ln3_kernel<<<MM, 256>>>(h, ctx, k, ln2w + (size_t)i * DD, ln2b + (size_t)i * DD);
    }

    cudaMemcpyAsync(d_out, h, sizeof(float) * (size_t)out_size, cudaMemcpyDeviceToDevice);
}